// round 1
// baseline (speedup 1.0000x reference)
#include <cuda_runtime.h>
#include <math.h>
#include <stdint.h>

// Problem constants (fixed shapes for this problem instance)
#define BB   2
#define SS   2048          // T*H*W
#define NTOK 4096          // BB*SS
#define DD   2048
#define EE   16
#define II   2048
#define CAP  640           // 2 * ceil(NTOK/EE * 1.25)

// ---------------- scratch (static device globals; no allocation) ----------------
__device__ float g_H[EE * CAP * II];     // gate*up activations  (80 MB)
__device__ float g_Y[EE * CAP * DD];     // expert outputs       (80 MB)
__device__ int   g_top[NTOK * 2];        // top-2 expert ids per token
__device__ float g_w[NTOK * 2];          // normalized top-2 probs
__device__ int   g_slot[NTOK * 2];       // slot index (e*CAP+pos) or -1 (dropped)
__device__ int   g_tok[EE * CAP];        // token id per slot
__device__ int   g_cnt[EE];              // filled slots per expert (<= CAP)

__device__ __forceinline__ float silu_f(float p) {
    return p / (1.0f + __expf(-p));
}

// ---------------- 1. router: logits -> softmax -> top2 -> normalized probs ------
__global__ void router_kernel(const float* __restrict__ hs, const float* __restrict__ wg) {
    int n = blockIdx.x;
    int b = n & 1;          // n % BB
    int s = n >> 1;         // n / BB
    const float* tok = hs + (size_t)b * SS * DD + (size_t)s * DD;

    float acc[EE];
#pragma unroll
    for (int e = 0; e < EE; e++) acc[e] = 0.0f;

    for (int d = threadIdx.x; d < DD; d += 128) {
        float x = tok[d];
#pragma unroll
        for (int e = 0; e < EE; e++) acc[e] += x * wg[e * DD + d];
    }
    // warp butterfly
#pragma unroll
    for (int e = 0; e < EE; e++) {
#pragma unroll
        for (int off = 16; off > 0; off >>= 1)
            acc[e] += __shfl_xor_sync(0xffffffffu, acc[e], off);
    }
    __shared__ float red[4][EE];
    int warp = threadIdx.x >> 5;
    int lane = threadIdx.x & 31;
    if (lane == 0) {
#pragma unroll
        for (int e = 0; e < EE; e++) red[warp][e] = acc[e];
    }
    __syncthreads();
    if (threadIdx.x == 0) {
        float g[EE];
#pragma unroll
        for (int e = 0; e < EE; e++)
            g[e] = red[0][e] + red[1][e] + red[2][e] + red[3][e];
        // softmax (fp32)
        float mx = g[0];
#pragma unroll
        for (int e = 1; e < EE; e++) mx = fmaxf(mx, g[e]);
        float sum = 0.0f;
#pragma unroll
        for (int e = 0; e < EE; e++) { g[e] = __expf(g[e] - mx); sum += g[e]; }
        float inv = 1.0f / sum;
#pragma unroll
        for (int e = 0; e < EE; e++) g[e] *= inv;
        // top-2, ties -> lowest index (strict >)
        int e1 = 0; float v1 = g[0];
#pragma unroll
        for (int e = 1; e < EE; e++) { if (g[e] > v1) { v1 = g[e]; e1 = e; } }
        int e2 = -1; float v2 = -1.0f;
#pragma unroll
        for (int e = 0; e < EE; e++) { if (e != e1 && g[e] > v2) { v2 = g[e]; e2 = e; } }
        float denom = v1 + v2;
        const float EPS = 1.1920929e-07f;
        if (denom < EPS) denom = EPS;
        g_top[2 * n]     = e1;
        g_top[2 * n + 1] = e2;
        g_w[2 * n]       = v1 / denom;
        g_w[2 * n + 1]   = v2 / denom;
    }
}

// ---------------- 2. capacity assignment (deterministic, topk-major cumsum) -----
__global__ void assign_kernel() {
    int e = blockIdx.x;           // one block per expert, 256 threads
    __shared__ int warpsum[8];
    __shared__ int s_running;
    if (threadIdx.x == 0) s_running = 0;
    __syncthreads();

    int lane = threadIdx.x & 31;
    int warp = threadIdx.x >> 5;

    for (int k = 0; k < 2; k++) {
        for (int c0 = 0; c0 < NTOK; c0 += 256) {
            int n = c0 + threadIdx.x;
            int f = (g_top[2 * n + k] == e) ? 1 : 0;
            unsigned bal = __ballot_sync(0xffffffffu, f);
            int lpre = __popc(bal & ((1u << lane) - 1u));
            if (lane == 0) warpsum[warp] = __popc(bal);
            __syncthreads();
            int wpre = 0, tot = 0;
#pragma unroll
            for (int w = 0; w < 8; w++) {
                int v = warpsum[w];
                if (w < warp) wpre += v;
                tot += v;
            }
            int pos = s_running + wpre + lpre;
            if (f) {
                if (pos < CAP) {
                    g_slot[2 * n + k] = e * CAP + pos;
                    g_tok[e * CAP + pos] = n;
                } else {
                    g_slot[2 * n + k] = -1;   // overflow drop
                }
            }
            __syncthreads();
            if (threadIdx.x == 0) s_running += tot;
            __syncthreads();
        }
    }
    if (threadIdx.x == 0) g_cnt[e] = (s_running < CAP) ? s_running : CAP;
}

// ---------------- 3. fused gate+up GEMM + SwiGLU: H = silu(X gp^T) * (X up^T) ----
// Tile: BM=128, BN=64, BK=16, 256 threads, 8x4 per thread (x2 outputs)
__global__ __launch_bounds__(256, 2) void ffn1_kernel(
    const float* __restrict__ hs, const float* __restrict__ gp, const float* __restrict__ up) {
    int e = blockIdx.z;
    int count = g_cnt[e];
    int m0 = blockIdx.y * 128;
    if (m0 >= count) return;
    int n0 = blockIdx.x * 64;

    const float* B1 = gp + (size_t)e * II * DD;
    const float* B2 = up + (size_t)e * II * DD;

    __shared__ float As[16][128];
    __shared__ float Bs1[16][64];
    __shared__ float Bs2[16][64];
    __shared__ unsigned s_aoff[128];

    int tid = threadIdx.x;
    if (tid < 128) {
        unsigned off = 0;
        int m = m0 + tid;
        if (m < count) {
            int t = g_tok[e * CAP + m];
            off = (unsigned)((t & 1) * (SS * DD) + (t >> 1) * DD);
        }
        s_aoff[tid] = off;
    }
    __syncthreads();

    int arow  = tid >> 2;            // 0..63
    int acol4 = (tid & 3) << 2;      // 0,4,8,12
    int tr = tid >> 4;               // 0..15 -> rows tr*8..
    int tc = tid & 15;               // 0..15 -> cols tc*4..

    float accP[8][4];
    float accQ[8][4];
#pragma unroll
    for (int i = 0; i < 8; i++)
#pragma unroll
        for (int j = 0; j < 4; j++) { accP[i][j] = 0.0f; accQ[i][j] = 0.0f; }

    for (int k0 = 0; k0 < DD; k0 += 16) {
        // A tile (gather via token offsets), rows arow and arow+64
#pragma unroll
        for (int r = 0; r < 2; r++) {
            int m = arow + r * 64;
            float4 v = make_float4(0.f, 0.f, 0.f, 0.f);
            if (m0 + m < count)
                v = *(const float4*)(hs + (size_t)s_aoff[m] + k0 + acol4);
            As[acol4 + 0][m] = v.x;
            As[acol4 + 1][m] = v.y;
            As[acol4 + 2][m] = v.z;
            As[acol4 + 3][m] = v.w;
        }
        // B tiles
        {
            int i  = tid >> 2;          // 0..63
            int kk = (tid & 3) << 2;
            float4 v1 = *(const float4*)(B1 + (size_t)(n0 + i) * DD + k0 + kk);
            float4 v2 = *(const float4*)(B2 + (size_t)(n0 + i) * DD + k0 + kk);
            Bs1[kk + 0][i] = v1.x; Bs1[kk + 1][i] = v1.y; Bs1[kk + 2][i] = v1.z; Bs1[kk + 3][i] = v1.w;
            Bs2[kk + 0][i] = v2.x; Bs2[kk + 1][i] = v2.y; Bs2[kk + 2][i] = v2.z; Bs2[kk + 3][i] = v2.w;
        }
        __syncthreads();
#pragma unroll
        for (int k = 0; k < 16; k++) {
            float a[8], b1[4], b2[4];
            float4 a0 = *(const float4*)&As[k][tr * 8];
            float4 a1 = *(const float4*)&As[k][tr * 8 + 4];
            a[0]=a0.x; a[1]=a0.y; a[2]=a0.z; a[3]=a0.w;
            a[4]=a1.x; a[5]=a1.y; a[6]=a1.z; a[7]=a1.w;
            float4 bb1 = *(const float4*)&Bs1[k][tc * 4];
            float4 bb2 = *(const float4*)&Bs2[k][tc * 4];
            b1[0]=bb1.x; b1[1]=bb1.y; b1[2]=bb1.z; b1[3]=bb1.w;
            b2[0]=bb2.x; b2[1]=bb2.y; b2[2]=bb2.z; b2[3]=bb2.w;
#pragma unroll
            for (int i = 0; i < 8; i++)
#pragma unroll
                for (int j = 0; j < 4; j++) {
                    accP[i][j] += a[i] * b1[j];
                    accQ[i][j] += a[i] * b2[j];
                }
        }
        __syncthreads();
    }
    // epilogue: H = silu(P)*Q  (rows beyond count are never read downstream)
    float* Hb = g_H + (size_t)e * CAP * II;
#pragma unroll
    for (int i = 0; i < 8; i++) {
        int row = m0 + tr * 8 + i;
        float4 o;
        o.x = silu_f(accP[i][0]) * accQ[i][0];
        o.y = silu_f(accP[i][1]) * accQ[i][1];
        o.z = silu_f(accP[i][2]) * accQ[i][2];
        o.w = silu_f(accP[i][3]) * accQ[i][3];
        *(float4*)(Hb + (size_t)row * II + n0 + tc * 4) = o;
    }
}

// ---------------- 4. down GEMM: Y = H dp^T -----------------------------------
// Tile: BM=128, BN=128, BK=8, 256 threads, 8x8 per thread
__global__ __launch_bounds__(256, 2) void ffn2_kernel(const float* __restrict__ dp) {
    int e = blockIdx.z;
    int count = g_cnt[e];
    int m0 = blockIdx.y * 128;
    if (m0 >= count) return;
    int n0 = blockIdx.x * 128;

    const float* A  = g_H + (size_t)e * CAP * II;
    const float* Bp = dp  + (size_t)e * DD * II;

    __shared__ float As[8][128];
    __shared__ float Bs[8][128];

    int tid = threadIdx.x;
    int lrow = tid >> 1;            // 0..127
    int lcol = (tid & 1) << 2;      // 0 or 4
    int tr = tid >> 4;              // rows tr*8..
    int tc = tid & 15;              // cols tc*8..

    float acc[8][8];
#pragma unroll
    for (int i = 0; i < 8; i++)
#pragma unroll
        for (int j = 0; j < 8; j++) acc[i][j] = 0.0f;

    for (int k0 = 0; k0 < II; k0 += 8) {
        float4 va = make_float4(0.f, 0.f, 0.f, 0.f);
        if (m0 + lrow < count)
            va = *(const float4*)(A + (size_t)(m0 + lrow) * II + k0 + lcol);
        float4 vb = *(const float4*)(Bp + (size_t)(n0 + lrow) * II + k0 + lcol);
        As[lcol + 0][lrow] = va.x; As[lcol + 1][lrow] = va.y;
        As[lcol + 2][lrow] = va.z; As[lcol + 3][lrow] = va.w;
        Bs[lcol + 0][lrow] = vb.x; Bs[lcol + 1][lrow] = vb.y;
        Bs[lcol + 2][lrow] = vb.z; Bs[lcol + 3][lrow] = vb.w;
        __syncthreads();
#pragma unroll
        for (int k = 0; k < 8; k++) {
            float a[8], b[8];
            float4 a0 = *(const float4*)&As[k][tr * 8];
            float4 a1 = *(const float4*)&As[k][tr * 8 + 4];
            a[0]=a0.x; a[1]=a0.y; a[2]=a0.z; a[3]=a0.w;
            a[4]=a1.x; a[5]=a1.y; a[6]=a1.z; a[7]=a1.w;
            float4 b0 = *(const float4*)&Bs[k][tc * 8];
            float4 b1 = *(const float4*)&Bs[k][tc * 8 + 4];
            b[0]=b0.x; b[1]=b0.y; b[2]=b0.z; b[3]=b0.w;
            b[4]=b1.x; b[5]=b1.y; b[6]=b1.z; b[7]=b1.w;
#pragma unroll
            for (int i = 0; i < 8; i++)
#pragma unroll
                for (int j = 0; j < 8; j++)
                    acc[i][j] += a[i] * b[j];
        }
        __syncthreads();
    }
    float* Yb = g_Y + (size_t)e * CAP * DD;
#pragma unroll
    for (int i = 0; i < 8; i++) {
        int row = m0 + tr * 8 + i;
        float* dst = Yb + (size_t)row * DD + n0 + tc * 8;
        float4 o0 = make_float4(acc[i][0], acc[i][1], acc[i][2], acc[i][3]);
        float4 o1 = make_float4(acc[i][4], acc[i][5], acc[i][6], acc[i][7]);
        *(float4*)(dst)     = o0;
        *(float4*)(dst + 4) = o1;
    }
}

// ---------------- 5. combine: out[n] = sum_k w_k * Y[slot_k] -------------------
__global__ void combine_kernel(float* __restrict__ out) {
    int n = blockIdx.x;
    int s0 = g_slot[2 * n];
    int s1 = g_slot[2 * n + 1];
    float w0 = g_w[2 * n];
    float w1 = g_w[2 * n + 1];
    int b = n & 1;
    int s = n >> 1;
    float* o = out + (size_t)b * SS * DD + (size_t)s * DD;
    const float* y0 = (s0 >= 0) ? (g_Y + (size_t)s0 * DD) : 0;
    const float* y1 = (s1 >= 0) ? (g_Y + (size_t)s1 * DD) : 0;

    for (int d4 = threadIdx.x; d4 < DD / 4; d4 += 256) {
        float4 v = make_float4(0.f, 0.f, 0.f, 0.f);
        if (y0) {
            float4 a = *(const float4*)(y0 + d4 * 4);
            v.x += w0 * a.x; v.y += w0 * a.y; v.z += w0 * a.z; v.w += w0 * a.w;
        }
        if (y1) {
            float4 a = *(const float4*)(y1 + d4 * 4);
            v.x += w1 * a.x; v.y += w1 * a.y; v.z += w1 * a.z; v.w += w1 * a.w;
        }
        *(float4*)(o + d4 * 4) = v;
    }
}

// ---------------- launch -------------------------------------------------------
extern "C" void kernel_launch(void* const* d_in, const int* in_sizes, int n_in,
                              void* d_out, int out_size) {
    (void)in_sizes; (void)n_in; (void)out_size;
    const float* hs = (const float*)d_in[0];
    const float* wg = (const float*)d_in[1];
    const float* gp = (const float*)d_in[2];
    const float* up = (const float*)d_in[3];
    const float* dp = (const float*)d_in[4];
    float* out = (float*)d_out;

    router_kernel<<<NTOK, 128>>>(hs, wg);
    assign_kernel<<<EE, 256>>>();
    ffn1_kernel<<<dim3(II / 64, CAP / 128, EE), 256>>>(hs, gp, up);
    ffn2_kernel<<<dim3(DD / 128, CAP / 128, EE), 256>>>(dp);
    combine_kernel<<<NTOK, 256>>>(out);
}

// round 3
// speedup vs baseline: 1.5847x; 1.5847x over previous
#include <cuda_runtime.h>
#include <cuda_bf16.h>
#include <math.h>
#include <stdint.h>

#define BB    2
#define SS    2048
#define NTOK  4096
#define DD    2048
#define EE    16
#define CAP   640
#define SLOTP 768                 // padded slots per expert (3 x BM=256)
#define KK    2048
#define NCH   192                 // K' = 3*2048 split-GEMM chunks of 32

typedef __nv_bfloat16 bf16;

// ---------------- scratch ----------------
__device__ bf16  g_Xh[(size_t)EE * SLOTP * KK];
__device__ bf16  g_Xl[(size_t)EE * SLOTP * KK];
__device__ bf16  g_Gh[(size_t)EE * KK * KK];
__device__ bf16  g_Gl[(size_t)EE * KK * KK];
__device__ bf16  g_Uh[(size_t)EE * KK * KK];
__device__ bf16  g_Ul[(size_t)EE * KK * KK];
__device__ bf16  g_Dh[(size_t)EE * KK * KK];
__device__ bf16  g_Dl[(size_t)EE * KK * KK];
__device__ float g_P [(size_t)EE * SLOTP * KK];
__device__ float g_Q [(size_t)EE * SLOTP * KK];
__device__ bf16  g_Hh[(size_t)EE * SLOTP * KK];
__device__ bf16  g_Hl[(size_t)EE * SLOTP * KK];
__device__ float g_Y [(size_t)EE * SLOTP * KK];
__device__ int   g_top[NTOK * 2];
__device__ float g_w[NTOK * 2];
__device__ int   g_slot[NTOK * 2];
__device__ int   g_tok[EE * CAP];
__device__ int   g_cnt[EE];

static __device__ __forceinline__ float silu_f(float p) { return p / (1.0f + __expf(-p)); }

static __device__ __forceinline__ uint32_t smem_u32(const void* p) {
    uint32_t a;
    asm("{ .reg .u64 t; cvta.to.shared.u64 t, %1; cvt.u32.u64 %0, t; }" : "=r"(a) : "l"(p));
    return a;
}
#define CP16(dst, src) asm volatile("cp.async.cg.shared.global [%0], [%1], 16;" :: "r"(dst), "l"(src))
#define CP_COMMIT()    asm volatile("cp.async.commit_group;")
#define CP_WAIT2()     asm volatile("cp.async.wait_group 2;")
#define CP_WAIT0()     asm volatile("cp.async.wait_group 0;")

static __device__ __forceinline__ void ldsm4(uint32_t* r, uint32_t a) {
    asm volatile("ldmatrix.sync.aligned.m8n8.x4.shared.b16 {%0,%1,%2,%3}, [%4];"
                 : "=r"(r[0]), "=r"(r[1]), "=r"(r[2]), "=r"(r[3]) : "r"(a));
}
static __device__ __forceinline__ void mma_bf16(float* c, const uint32_t* a, uint32_t b0, uint32_t b1) {
    asm volatile("mma.sync.aligned.m16n8k16.row.col.f32.bf16.bf16.f32 "
                 "{%0,%1,%2,%3}, {%4,%5,%6,%7}, {%8,%9}, {%0,%1,%2,%3};"
                 : "+f"(c[0]), "+f"(c[1]), "+f"(c[2]), "+f"(c[3])
                 : "r"(a[0]), "r"(a[1]), "r"(a[2]), "r"(a[3]), "r"(b0), "r"(b1));
}
static __device__ __forceinline__ void split2(float x, uint16_t& h, uint16_t& l) {
    bf16 hb = __float2bfloat16_rn(x);
    bf16 lb = __float2bfloat16_rn(x - __bfloat162float(hb));
    h = __bfloat16_as_ushort(hb);
    l = __bfloat16_as_ushort(lb);
}

// ---------------- router ----------------
__global__ void router_kernel(const float* __restrict__ hs, const float* __restrict__ wg) {
    int n = blockIdx.x, b = n & 1, s = n >> 1;
    const float* tok = hs + (size_t)b * SS * DD + (size_t)s * DD;
    float acc[EE];
#pragma unroll
    for (int e = 0; e < EE; e++) acc[e] = 0.0f;
    for (int d = threadIdx.x; d < DD; d += 128) {
        float x = tok[d];
#pragma unroll
        for (int e = 0; e < EE; e++) acc[e] += x * wg[e * DD + d];
    }
#pragma unroll
    for (int e = 0; e < EE; e++)
#pragma unroll
        for (int off = 16; off > 0; off >>= 1)
            acc[e] += __shfl_xor_sync(0xffffffffu, acc[e], off);
    __shared__ float red[4][EE];
    int warp = threadIdx.x >> 5, lane = threadIdx.x & 31;
    if (lane == 0)
#pragma unroll
        for (int e = 0; e < EE; e++) red[warp][e] = acc[e];
    __syncthreads();
    if (threadIdx.x == 0) {
        float g[EE];
#pragma unroll
        for (int e = 0; e < EE; e++) g[e] = red[0][e] + red[1][e] + red[2][e] + red[3][e];
        float mx = g[0];
#pragma unroll
        for (int e = 1; e < EE; e++) mx = fmaxf(mx, g[e]);
        float sum = 0.0f;
#pragma unroll
        for (int e = 0; e < EE; e++) { g[e] = __expf(g[e] - mx); sum += g[e]; }
        float inv = 1.0f / sum;
#pragma unroll
        for (int e = 0; e < EE; e++) g[e] *= inv;
        int e1 = 0; float v1 = g[0];
#pragma unroll
        for (int e = 1; e < EE; e++) if (g[e] > v1) { v1 = g[e]; e1 = e; }
        int e2 = -1; float v2 = -1.0f;
#pragma unroll
        for (int e = 0; e < EE; e++) if (e != e1 && g[e] > v2) { v2 = g[e]; e2 = e; }
        float denom = v1 + v2;
        const float EPS = 1.1920929e-07f;
        if (denom < EPS) denom = EPS;
        g_top[2 * n] = e1; g_top[2 * n + 1] = e2;
        g_w[2 * n] = v1 / denom; g_w[2 * n + 1] = v2 / denom;
    }
}

// ---------------- assign ----------------
__global__ void assign_kernel() {
    int e = blockIdx.x;
    __shared__ int warpsum[8];
    __shared__ int s_running;
    if (threadIdx.x == 0) s_running = 0;
    __syncthreads();
    int lane = threadIdx.x & 31, warp = threadIdx.x >> 5;
    for (int k = 0; k < 2; k++)
        for (int c0 = 0; c0 < NTOK; c0 += 256) {
            int n = c0 + threadIdx.x;
            int f = (g_top[2 * n + k] == e) ? 1 : 0;
            unsigned bal = __ballot_sync(0xffffffffu, f);
            int lpre = __popc(bal & ((1u << lane) - 1u));
            if (lane == 0) warpsum[warp] = __popc(bal);
            __syncthreads();
            int wpre = 0, tot = 0;
#pragma unroll
            for (int w = 0; w < 8; w++) { int v = warpsum[w]; if (w < warp) wpre += v; tot += v; }
            int pos = s_running + wpre + lpre;
            if (f) {
                if (pos < CAP) { g_slot[2 * n + k] = e * SLOTP + pos; g_tok[e * CAP + pos] = n; }
                else           { g_slot[2 * n + k] = -1; }
            }
            __syncthreads();
            if (threadIdx.x == 0) s_running += tot;
            __syncthreads();
        }
    if (threadIdx.x == 0) g_cnt[e] = (s_running < CAP) ? s_running : CAP;
}

// ---------------- prep: weight split fp32 -> bf16 hi/lo ----------------
__global__ void prep_w_kernel(const float* __restrict__ src, bf16* __restrict__ dh, bf16* __restrict__ dl) {
    size_t i4 = (size_t)blockIdx.x * 256 + threadIdx.x;   // 4 elems each
    float4 v = *(const float4*)(src + i4 * 4);
    uint16_t h[4], l[4];
    split2(v.x, h[0], l[0]); split2(v.y, h[1], l[1]);
    split2(v.z, h[2], l[2]); split2(v.w, h[3], l[3]);
    *(uint2*)(dh + i4 * 4) = make_uint2((uint32_t)h[0] | ((uint32_t)h[1] << 16),
                                        (uint32_t)h[2] | ((uint32_t)h[3] << 16));
    *(uint2*)(dl + i4 * 4) = make_uint2((uint32_t)l[0] | ((uint32_t)l[1] << 16),
                                        (uint32_t)l[2] | ((uint32_t)l[3] << 16));
}

// ---------------- prep: gather tokens into padded slot slabs ----------------
__global__ void prep_x_kernel(const float* __restrict__ hs) {
    int e = blockIdx.y, p = blockIdx.x;
    int count = g_cnt[e];
    size_t row = (size_t)(e * SLOTP + p) * KK;
    if (p >= count) {
        for (int j = threadIdx.x; j < KK / 4; j += 256) {
            *(uint2*)(g_Xh + row + j * 4) = make_uint2(0, 0);
            *(uint2*)(g_Xl + row + j * 4) = make_uint2(0, 0);
        }
        return;
    }
    int t = g_tok[e * CAP + p];
    const float* src = hs + ((size_t)(t & 1) * SS + (size_t)(t >> 1)) * DD;
    for (int j = threadIdx.x; j < KK / 4; j += 256) {
        float4 v = *(const float4*)(src + j * 4);
        uint16_t h[4], l[4];
        split2(v.x, h[0], l[0]); split2(v.y, h[1], l[1]);
        split2(v.z, h[2], l[2]); split2(v.w, h[3], l[3]);
        *(uint2*)(g_Xh + row + j * 4) = make_uint2((uint32_t)h[0] | ((uint32_t)h[1] << 16),
                                                   (uint32_t)h[2] | ((uint32_t)h[3] << 16));
        *(uint2*)(g_Xl + row + j * 4) = make_uint2((uint32_t)l[0] | ((uint32_t)l[1] << 16),
                                                   (uint32_t)l[2] | ((uint32_t)l[3] << 16));
    }
}

// ---------------- split-K' GEMM: C[M][N] += A[M][K']*B[N][K']^T ----------------
// BM=256, BN=128, 512 threads, 16 warps (8 M x 2 N), warp tile 32x64.
// SMEM rows padded to 80B -> conflict-free ldmatrix. 4-stage cp.async ring.
#define STG_BYTES 30720           // A: 256*80 = 20480, B: 128*80 = 10240
#define GSMEM     (4 * STG_BYTES) // 122880

__global__ void __launch_bounds__(512, 1)
gemm_kernel(const bf16* __restrict__ Ah, const bf16* __restrict__ Al,
            const bf16* __restrict__ Bh, const bf16* __restrict__ Bl,
            float* __restrict__ C) {
    int e = blockIdx.z;
    int count = g_cnt[e];
    int m0 = blockIdx.y * 256;
    if (m0 >= count) return;
    int n0 = blockIdx.x * 128;

    extern __shared__ char smem[];
    uint32_t sb = smem_u32(smem);
    int tid = threadIdx.x, lane = tid & 31, w = tid >> 5;
    int wm = w >> 1, wn = w & 1;

    const bf16* A_h = Ah + ((size_t)e * SLOTP + m0) * KK;
    const bf16* A_l = Al + ((size_t)e * SLOTP + m0) * KK;
    const bf16* B_h = Bh + (size_t)e * KK * KK + (size_t)n0 * KK;
    const bf16* B_l = Bl + (size_t)e * KK * KK + (size_t)n0 * KK;

    // per-thread cp.async targets
    int ar0 = tid >> 1;                 // rows 0..255 (2 chunks each row half)
    // A: ids tid and tid+512 -> row=id>>2, sub=id&3
    // B: row=tid>>2, sub=tid&3
    // ldmatrix source offsets (within stage)
    uint32_t aBase[2];
#pragma unroll
    for (int mt = 0; mt < 2; mt++)
        aBase[mt] = (uint32_t)((wm * 32 + mt * 16 + (lane & 15)) * 80 + ((lane >> 4) << 4));
    uint32_t bBase[4];
#pragma unroll
    for (int p = 0; p < 4; p++) {
        int grp = lane >> 3, wi = lane & 7;
        bBase[p] = (uint32_t)(20480 + (wn * 64 + p * 16 + ((grp >> 1) << 3) + wi) * 80 + ((grp & 1) << 4));
    }
    (void)ar0;

    float acc[2][8][4];
#pragma unroll
    for (int i = 0; i < 2; i++)
#pragma unroll
        for (int j = 0; j < 8; j++)
#pragma unroll
            for (int q = 0; q < 4; q++) acc[i][j][q] = 0.0f;

    // chunk loader
    auto load_chunk = [&](int c, int st) {
        int r = c >> 6;
        int k0 = (c & 63) << 5;
        const bf16* As = (r == 1) ? A_l : A_h;
        const bf16* Bs = (r == 2) ? B_l : B_h;
        uint32_t stb = sb + st * STG_BYTES;
#pragma unroll
        for (int i = 0; i < 2; i++) {
            int id = tid + i * 512;
            int row = id >> 2, sub = id & 3;
            CP16(stb + row * 80 + sub * 16, As + (size_t)row * KK + k0 + sub * 8);
        }
        {
            int row = tid >> 2, sub = tid & 3;
            CP16(stb + 20480 + row * 80 + sub * 16, Bs + (size_t)row * KK + k0 + sub * 8);
        }
        CP_COMMIT();
    };

#pragma unroll
    for (int s = 0; s < 3; s++) load_chunk(s, s);

    for (int c = 0; c < NCH; c++) {
        CP_WAIT2();
        __syncthreads();
        if (c + 3 < NCH) load_chunk(c + 3, (c + 3) & 3);
        uint32_t base = sb + (c & 3) * STG_BYTES;
#pragma unroll
        for (int ks = 0; ks < 2; ks++) {
            uint32_t a[2][4], b[4][4];
            ldsm4(a[0], base + aBase[0] + ks * 32);
            ldsm4(a[1], base + aBase[1] + ks * 32);
#pragma unroll
            for (int p = 0; p < 4; p++) ldsm4(b[p], base + bBase[p] + ks * 32);
#pragma unroll
            for (int mt = 0; mt < 2; mt++)
#pragma unroll
                for (int p = 0; p < 4; p++) {
                    mma_bf16(acc[mt][2 * p],     a[mt], b[p][0], b[p][1]);
                    mma_bf16(acc[mt][2 * p + 1], a[mt], b[p][2], b[p][3]);
                }
        }
    }
    CP_WAIT0();

    // epilogue
    float* Cb = C + ((size_t)e * SLOTP + m0) * KK + n0;
#pragma unroll
    for (int mt = 0; mt < 2; mt++) {
        int row = wm * 32 + mt * 16 + (lane >> 2);
#pragma unroll
        for (int nt = 0; nt < 8; nt++) {
            int col = wn * 64 + nt * 8 + ((lane & 3) << 1);
            *(float2*)(Cb + (size_t)row * KK + col)       = make_float2(acc[mt][nt][0], acc[mt][nt][1]);
            *(float2*)(Cb + (size_t)(row + 8) * KK + col) = make_float2(acc[mt][nt][2], acc[mt][nt][3]);
        }
    }
}

// ---------------- swiglu: H = silu(P)*Q -> bf16 hi/lo ----------------
__global__ void swiglu_kernel() {
    size_t i4 = (size_t)blockIdx.x * 256 + threadIdx.x;   // 4 elems
    float4 p = *(const float4*)(g_P + i4 * 4);
    float4 q = *(const float4*)(g_Q + i4 * 4);
    float h0 = silu_f(p.x) * q.x, h1 = silu_f(p.y) * q.y;
    float h2 = silu_f(p.z) * q.z, h3 = silu_f(p.w) * q.w;
    uint16_t h[4], l[4];
    split2(h0, h[0], l[0]); split2(h1, h[1], l[1]);
    split2(h2, h[2], l[2]); split2(h3, h[3], l[3]);
    *(uint2*)(g_Hh + i4 * 4) = make_uint2((uint32_t)h[0] | ((uint32_t)h[1] << 16),
                                          (uint32_t)h[2] | ((uint32_t)h[3] << 16));
    *(uint2*)(g_Hl + i4 * 4) = make_uint2((uint32_t)l[0] | ((uint32_t)l[1] << 16),
                                          (uint32_t)l[2] | ((uint32_t)l[3] << 16));
}

// ---------------- combine ----------------
__global__ void combine_kernel(float* __restrict__ out) {
    int n = blockIdx.x;
    int s0 = g_slot[2 * n], s1 = g_slot[2 * n + 1];
    float w0 = g_w[2 * n], w1 = g_w[2 * n + 1];
    int b = n & 1, s = n >> 1;
    float* o = out + (size_t)b * SS * DD + (size_t)s * DD;
    const float* y0 = (s0 >= 0) ? (g_Y + (size_t)s0 * KK) : 0;
    const float* y1 = (s1 >= 0) ? (g_Y + (size_t)s1 * KK) : 0;
    for (int d4 = threadIdx.x; d4 < DD / 4; d4 += 256) {
        float4 v = make_float4(0.f, 0.f, 0.f, 0.f);
        if (y0) {
            float4 a = *(const float4*)(y0 + d4 * 4);
            v.x += w0 * a.x; v.y += w0 * a.y; v.z += w0 * a.z; v.w += w0 * a.w;
        }
        if (y1) {
            float4 a = *(const float4*)(y1 + d4 * 4);
            v.x += w1 * a.x; v.y += w1 * a.y; v.z += w1 * a.z; v.w += w1 * a.w;
        }
        *(float4*)(o + d4 * 4) = v;
    }
}

// ---------------- launch ----------------
extern "C" void kernel_launch(void* const* d_in, const int* in_sizes, int n_in,
                              void* d_out, int out_size) {
    (void)in_sizes; (void)n_in; (void)out_size;
    const float* hs = (const float*)d_in[0];
    const float* wg = (const float*)d_in[1];
    const float* gp = (const float*)d_in[2];
    const float* up = (const float*)d_in[3];
    const float* dp = (const float*)d_in[4];
    float* out = (float*)d_out;

    static int smem_set = 0;
    if (!smem_set) {
        cudaFuncSetAttribute(gemm_kernel, cudaFuncAttributeMaxDynamicSharedMemorySize, GSMEM);
        smem_set = 1;
    }

    bf16 *Gh, *Gl, *Uh, *Ul, *Dh, *Dl, *Xh, *Xl, *Hh, *Hl;
    float *P, *Q, *Y;
    cudaGetSymbolAddress((void**)&Gh, g_Gh); cudaGetSymbolAddress((void**)&Gl, g_Gl);
    cudaGetSymbolAddress((void**)&Uh, g_Uh); cudaGetSymbolAddress((void**)&Ul, g_Ul);
    cudaGetSymbolAddress((void**)&Dh, g_Dh); cudaGetSymbolAddress((void**)&Dl, g_Dl);
    cudaGetSymbolAddress((void**)&Xh, g_Xh); cudaGetSymbolAddress((void**)&Xl, g_Xl);
    cudaGetSymbolAddress((void**)&Hh, g_Hh); cudaGetSymbolAddress((void**)&Hl, g_Hl);
    cudaGetSymbolAddress((void**)&P, g_P);   cudaGetSymbolAddress((void**)&Q, g_Q);
    cudaGetSymbolAddress((void**)&Y, g_Y);

    const int WBLK = (int)(((size_t)EE * KK * KK) / 4 / 256);   // 65536
    prep_w_kernel<<<WBLK, 256>>>(gp, Gh, Gl);
    prep_w_kernel<<<WBLK, 256>>>(up, Uh, Ul);
    prep_w_kernel<<<WBLK, 256>>>(dp, Dh, Dl);

    router_kernel<<<NTOK, 128>>>(hs, wg);
    assign_kernel<<<EE, 256>>>();
    prep_x_kernel<<<dim3(SLOTP, EE), 256>>>(hs);

    dim3 ggrid(KK / 128, SLOTP / 256, EE);
    gemm_kernel<<<ggrid, 512, GSMEM>>>(Xh, Xl, Gh, Gl, P);
    gemm_kernel<<<ggrid, 512, GSMEM>>>(Xh, Xl, Uh, Ul, Q);

    const int SBLK = (int)(((size_t)EE * SLOTP * KK) / 4 / 256); // 24576
    swiglu_kernel<<<SBLK, 256>>>();

    gemm_kernel<<<ggrid, 512, GSMEM>>>(Hh, Hl, Dh, Dl, Y);
    combine_kernel<<<NTOK, 256>>>(out);
}

// round 4
// speedup vs baseline: 1.8138x; 1.1446x over previous
#include <cuda_runtime.h>
#include <cuda_bf16.h>
#include <math.h>
#include <stdint.h>

#define BB    2
#define SS    2048
#define NTOK  4096
#define DD    2048
#define EE    16
#define CAP   640
#define SLOTP 768
#define KK    2048
#define NCH2  96                  // K' = 3*2048 in chunks of 64

typedef __nv_bfloat16 bf16;

// ---------------- scratch ----------------
__device__ bf16  g_Xh[(size_t)EE * SLOTP * KK];
__device__ bf16  g_Xl[(size_t)EE * SLOTP * KK];
__device__ bf16  g_Gh[(size_t)EE * KK * KK];
__device__ bf16  g_Gl[(size_t)EE * KK * KK];
__device__ bf16  g_Uh[(size_t)EE * KK * KK];
__device__ bf16  g_Ul[(size_t)EE * KK * KK];
__device__ bf16  g_Dh[(size_t)EE * KK * KK];
__device__ bf16  g_Dl[(size_t)EE * KK * KK];
__device__ float g_P [(size_t)EE * SLOTP * KK];
__device__ float g_Q [(size_t)EE * SLOTP * KK];
__device__ bf16  g_Hh[(size_t)EE * SLOTP * KK];
__device__ bf16  g_Hl[(size_t)EE * SLOTP * KK];
__device__ float g_Y [(size_t)EE * SLOTP * KK];
__device__ int   g_top[NTOK * 2];
__device__ float g_w[NTOK * 2];
__device__ int   g_slot[NTOK * 2];
__device__ int   g_tok[EE * CAP];
__device__ int   g_cnt[EE];

static __device__ __forceinline__ float silu_f(float p) { return p / (1.0f + __expf(-p)); }

static __device__ __forceinline__ uint32_t smem_u32(const void* p) {
    uint32_t a;
    asm("{ .reg .u64 t; cvta.to.shared.u64 t, %1; cvt.u32.u64 %0, t; }" : "=r"(a) : "l"(p));
    return a;
}
#define CP16(dst, src) asm volatile("cp.async.cg.shared.global [%0], [%1], 16;" :: "r"(dst), "l"(src))
#define CP_COMMIT()    asm volatile("cp.async.commit_group;")
#define CP_WAIT2()     asm volatile("cp.async.wait_group 2;")
#define CP_WAIT0()     asm volatile("cp.async.wait_group 0;")

static __device__ __forceinline__ void ldsm4(uint32_t* r, uint32_t a) {
    asm volatile("ldmatrix.sync.aligned.m8n8.x4.shared.b16 {%0,%1,%2,%3}, [%4];"
                 : "=r"(r[0]), "=r"(r[1]), "=r"(r[2]), "=r"(r[3]) : "r"(a));
}
static __device__ __forceinline__ void mma_bf16(float* c, const uint32_t* a, uint32_t b0, uint32_t b1) {
    asm volatile("mma.sync.aligned.m16n8k16.row.col.f32.bf16.bf16.f32 "
                 "{%0,%1,%2,%3}, {%4,%5,%6,%7}, {%8,%9}, {%0,%1,%2,%3};"
                 : "+f"(c[0]), "+f"(c[1]), "+f"(c[2]), "+f"(c[3])
                 : "r"(a[0]), "r"(a[1]), "r"(a[2]), "r"(a[3]), "r"(b0), "r"(b1));
}
static __device__ __forceinline__ void split2(float x, uint16_t& h, uint16_t& l) {
    bf16 hb = __float2bfloat16_rn(x);
    bf16 lb = __float2bfloat16_rn(x - __bfloat162float(hb));
    h = __bfloat16_as_ushort(hb);
    l = __bfloat16_as_ushort(lb);
}

// ---------------- router ----------------
__global__ void router_kernel(const float* __restrict__ hs, const float* __restrict__ wg) {
    int n = blockIdx.x, b = n & 1, s = n >> 1;
    const float* tok = hs + (size_t)b * SS * DD + (size_t)s * DD;
    float acc[EE];
#pragma unroll
    for (int e = 0; e < EE; e++) acc[e] = 0.0f;
    for (int d = threadIdx.x; d < DD; d += 128) {
        float x = tok[d];
#pragma unroll
        for (int e = 0; e < EE; e++) acc[e] += x * wg[e * DD + d];
    }
#pragma unroll
    for (int e = 0; e < EE; e++)
#pragma unroll
        for (int off = 16; off > 0; off >>= 1)
            acc[e] += __shfl_xor_sync(0xffffffffu, acc[e], off);
    __shared__ float red[4][EE];
    int warp = threadIdx.x >> 5, lane = threadIdx.x & 31;
    if (lane == 0)
#pragma unroll
        for (int e = 0; e < EE; e++) red[warp][e] = acc[e];
    __syncthreads();
    if (threadIdx.x == 0) {
        float g[EE];
#pragma unroll
        for (int e = 0; e < EE; e++) g[e] = red[0][e] + red[1][e] + red[2][e] + red[3][e];
        float mx = g[0];
#pragma unroll
        for (int e = 1; e < EE; e++) mx = fmaxf(mx, g[e]);
        float sum = 0.0f;
#pragma unroll
        for (int e = 0; e < EE; e++) { g[e] = __expf(g[e] - mx); sum += g[e]; }
        float inv = 1.0f / sum;
#pragma unroll
        for (int e = 0; e < EE; e++) g[e] *= inv;
        int e1 = 0; float v1 = g[0];
#pragma unroll
        for (int e = 1; e < EE; e++) if (g[e] > v1) { v1 = g[e]; e1 = e; }
        int e2 = -1; float v2 = -1.0f;
#pragma unroll
        for (int e = 0; e < EE; e++) if (e != e1 && g[e] > v2) { v2 = g[e]; e2 = e; }
        float denom = v1 + v2;
        const float EPS = 1.1920929e-07f;
        if (denom < EPS) denom = EPS;
        g_top[2 * n] = e1; g_top[2 * n + 1] = e2;
        g_w[2 * n] = v1 / denom; g_w[2 * n + 1] = v2 / denom;
    }
}

// ---------------- assign ----------------
__global__ void assign_kernel() {
    int e = blockIdx.x;
    __shared__ int warpsum[8];
    __shared__ int s_running;
    if (threadIdx.x == 0) s_running = 0;
    __syncthreads();
    int lane = threadIdx.x & 31, warp = threadIdx.x >> 5;
    for (int k = 0; k < 2; k++)
        for (int c0 = 0; c0 < NTOK; c0 += 256) {
            int n = c0 + threadIdx.x;
            int f = (g_top[2 * n + k] == e) ? 1 : 0;
            unsigned bal = __ballot_sync(0xffffffffu, f);
            int lpre = __popc(bal & ((1u << lane) - 1u));
            if (lane == 0) warpsum[warp] = __popc(bal);
            __syncthreads();
            int wpre = 0, tot = 0;
#pragma unroll
            for (int w = 0; w < 8; w++) { int v = warpsum[w]; if (w < warp) wpre += v; tot += v; }
            int pos = s_running + wpre + lpre;
            if (f) {
                if (pos < CAP) { g_slot[2 * n + k] = e * SLOTP + pos; g_tok[e * CAP + pos] = n; }
                else           { g_slot[2 * n + k] = -1; }
            }
            __syncthreads();
            if (threadIdx.x == 0) s_running += tot;
            __syncthreads();
        }
    if (threadIdx.x == 0) g_cnt[e] = (s_running < CAP) ? s_running : CAP;
}

// ---------------- prep: all 3 weights split fp32 -> bf16 hi/lo (one launch) ----
__global__ void prep_w_kernel(const float* __restrict__ gp, const float* __restrict__ up,
                              const float* __restrict__ dp,
                              bf16* __restrict__ Gh, bf16* __restrict__ Gl,
                              bf16* __restrict__ Uh, bf16* __restrict__ Ul,
                              bf16* __restrict__ Dh, bf16* __restrict__ Dl) {
    const float* src = (blockIdx.y == 0) ? gp : (blockIdx.y == 1) ? up : dp;
    bf16* dh = (blockIdx.y == 0) ? Gh : (blockIdx.y == 1) ? Uh : Dh;
    bf16* dl = (blockIdx.y == 0) ? Gl : (blockIdx.y == 1) ? Ul : Dl;
    size_t i4 = (size_t)blockIdx.x * 256 + threadIdx.x;
    float4 v = *(const float4*)(src + i4 * 4);
    uint16_t h[4], l[4];
    split2(v.x, h[0], l[0]); split2(v.y, h[1], l[1]);
    split2(v.z, h[2], l[2]); split2(v.w, h[3], l[3]);
    *(uint2*)(dh + i4 * 4) = make_uint2((uint32_t)h[0] | ((uint32_t)h[1] << 16),
                                        (uint32_t)h[2] | ((uint32_t)h[3] << 16));
    *(uint2*)(dl + i4 * 4) = make_uint2((uint32_t)l[0] | ((uint32_t)l[1] << 16),
                                        (uint32_t)l[2] | ((uint32_t)l[3] << 16));
}

// ---------------- prep: gather tokens into padded slot slabs ----------------
__global__ void prep_x_kernel(const float* __restrict__ hs) {
    int e = blockIdx.y, p = blockIdx.x;
    int count = g_cnt[e];
    size_t row = (size_t)(e * SLOTP + p) * KK;
    if (p >= count) {
        for (int j = threadIdx.x; j < KK / 4; j += 256) {
            *(uint2*)(g_Xh + row + j * 4) = make_uint2(0, 0);
            *(uint2*)(g_Xl + row + j * 4) = make_uint2(0, 0);
        }
        return;
    }
    int t = g_tok[e * CAP + p];
    const float* src = hs + ((size_t)(t & 1) * SS + (size_t)(t >> 1)) * DD;
    for (int j = threadIdx.x; j < KK / 4; j += 256) {
        float4 v = *(const float4*)(src + j * 4);
        uint16_t h[4], l[4];
        split2(v.x, h[0], l[0]); split2(v.y, h[1], l[1]);
        split2(v.z, h[2], l[2]); split2(v.w, h[3], l[3]);
        *(uint2*)(g_Xh + row + j * 4) = make_uint2((uint32_t)h[0] | ((uint32_t)h[1] << 16),
                                                   (uint32_t)h[2] | ((uint32_t)h[3] << 16));
        *(uint2*)(g_Xl + row + j * 4) = make_uint2((uint32_t)l[0] | ((uint32_t)l[1] << 16),
                                                   (uint32_t)l[2] | ((uint32_t)l[3] << 16));
    }
}

// ---------------- split-K' GEMM, K-chunk 64, 4-stage, reg double-buffer ----------
// BM=256, BN=128, 512 thr, 16 warps (8M x 2N), warp tile 32x64.
// SMEM row stride 144B (128 data + 16 pad) -> conflict-free ldmatrix.
#define ROWB  144
#define ASZ   (256 * ROWB)        // 36864
#define BSZ   (128 * ROWB)        // 18432
#define STG   (ASZ + BSZ)         // 55296
#define GSMEM (4 * STG)           // 221184

__global__ void __launch_bounds__(512, 1)
gemm_kernel(const bf16* __restrict__ Ah, const bf16* __restrict__ Al,
            const bf16* __restrict__ Bh, const bf16* __restrict__ Bl,
            float* __restrict__ C) {
    int e = blockIdx.z;
    int count = g_cnt[e];
    int m0 = blockIdx.y * 256;
    if (m0 >= count) return;
    int n0 = blockIdx.x * 128;

    extern __shared__ char smem[];
    uint32_t sb = smem_u32(smem);
    int tid = threadIdx.x, lane = tid & 31, w = tid >> 5;
    int wm = w >> 1, wn = w & 1;

    const bf16* A_h = Ah + ((size_t)e * SLOTP + m0) * KK;
    const bf16* A_l = Al + ((size_t)e * SLOTP + m0) * KK;
    const bf16* B_h = Bh + (size_t)e * KK * KK + (size_t)n0 * KK;
    const bf16* B_l = Bl + (size_t)e * KK * KK + (size_t)n0 * KK;

    uint32_t aBase[2];
#pragma unroll
    for (int mt = 0; mt < 2; mt++)
        aBase[mt] = (uint32_t)((wm * 32 + mt * 16 + (lane & 15)) * ROWB + ((lane >> 4) << 4));
    uint32_t bBase[4];
    {
        int grp = lane >> 3, wi = lane & 7;
#pragma unroll
        for (int p = 0; p < 4; p++)
            bBase[p] = (uint32_t)(ASZ + (wn * 64 + p * 16 + ((grp >> 1) << 3) + wi) * ROWB + ((grp & 1) << 4));
    }

    float acc[2][8][4];
#pragma unroll
    for (int i = 0; i < 2; i++)
#pragma unroll
        for (int j = 0; j < 8; j++)
#pragma unroll
            for (int q = 0; q < 4; q++) acc[i][j][q] = 0.0f;

    auto load_chunk = [&](int c, int st) {
        int r = c >> 5;
        int k0 = (c & 31) << 6;
        const bf16* As = (r == 1) ? A_l : A_h;
        const bf16* Bs = (r == 2) ? B_l : B_h;
        uint32_t stb = sb + st * STG;
#pragma unroll
        for (int i = 0; i < 4; i++) {          // A: 256 rows x 8 chunks of 16B
            int id = tid + i * 512;
            int row = id >> 3, sub = id & 7;
            CP16(stb + row * ROWB + sub * 16, As + (size_t)row * KK + k0 + sub * 8);
        }
#pragma unroll
        for (int i = 0; i < 2; i++) {          // B: 128 rows x 8 chunks
            int id = tid + i * 512;
            int row = id >> 3, sub = id & 7;
            CP16(stb + ASZ + row * ROWB + sub * 16, Bs + (size_t)row * KK + k0 + sub * 8);
        }
        CP_COMMIT();
    };

#pragma unroll
    for (int s = 0; s < 3; s++) load_chunk(s, s);

    uint32_t afr[2][2][4], bfr[2][4][4];
    for (int c = 0; c < NCH2; c++) {
        CP_WAIT2();
        __syncthreads();
        if (c + 3 < NCH2) load_chunk(c + 3, (c + 3) & 3);
        uint32_t base = sb + (c & 3) * STG;
        // preload ks=0 fragments
        ldsm4(afr[0][0], base + aBase[0]);
        ldsm4(afr[0][1], base + aBase[1]);
#pragma unroll
        for (int p = 0; p < 4; p++) ldsm4(bfr[0][p], base + bBase[p]);
#pragma unroll
        for (int ks = 0; ks < 4; ks++) {
            int cur = ks & 1, nxt = cur ^ 1;
            if (ks < 3) {
                uint32_t off = (uint32_t)((ks + 1) * 32);
                ldsm4(afr[nxt][0], base + aBase[0] + off);
                ldsm4(afr[nxt][1], base + aBase[1] + off);
#pragma unroll
                for (int p = 0; p < 4; p++) ldsm4(bfr[nxt][p], base + bBase[p] + off);
            }
#pragma unroll
            for (int mt = 0; mt < 2; mt++)
#pragma unroll
                for (int p = 0; p < 4; p++) {
                    mma_bf16(acc[mt][2 * p],     afr[cur][mt], bfr[cur][p][0], bfr[cur][p][1]);
                    mma_bf16(acc[mt][2 * p + 1], afr[cur][mt], bfr[cur][p][2], bfr[cur][p][3]);
                }
        }
    }
    CP_WAIT0();

    float* Cb = C + ((size_t)e * SLOTP + m0) * KK + n0;
#pragma unroll
    for (int mt = 0; mt < 2; mt++) {
        int row = wm * 32 + mt * 16 + (lane >> 2);
#pragma unroll
        for (int nt = 0; nt < 8; nt++) {
            int col = wn * 64 + nt * 8 + ((lane & 3) << 1);
            *(float2*)(Cb + (size_t)row * KK + col)       = make_float2(acc[mt][nt][0], acc[mt][nt][1]);
            *(float2*)(Cb + (size_t)(row + 8) * KK + col) = make_float2(acc[mt][nt][2], acc[mt][nt][3]);
        }
    }
}

// ---------------- swiglu ----------------
__global__ void swiglu_kernel() {
    size_t i4 = (size_t)blockIdx.x * 256 + threadIdx.x;
    float4 p = *(const float4*)(g_P + i4 * 4);
    float4 q = *(const float4*)(g_Q + i4 * 4);
    float h0 = silu_f(p.x) * q.x, h1 = silu_f(p.y) * q.y;
    float h2 = silu_f(p.z) * q.z, h3 = silu_f(p.w) * q.w;
    uint16_t h[4], l[4];
    split2(h0, h[0], l[0]); split2(h1, h[1], l[1]);
    split2(h2, h[2], l[2]); split2(h3, h[3], l[3]);
    *(uint2*)(g_Hh + i4 * 4) = make_uint2((uint32_t)h[0] | ((uint32_t)h[1] << 16),
                                          (uint32_t)h[2] | ((uint32_t)h[3] << 16));
    *(uint2*)(g_Hl + i4 * 4) = make_uint2((uint32_t)l[0] | ((uint32_t)l[1] << 16),
                                          (uint32_t)l[2] | ((uint32_t)l[3] << 16));
}

// ---------------- combine ----------------
__global__ void combine_kernel(float* __restrict__ out) {
    int n = blockIdx.x;
    int s0 = g_slot[2 * n], s1 = g_slot[2 * n + 1];
    float w0 = g_w[2 * n], w1 = g_w[2 * n + 1];
    int b = n & 1, s = n >> 1;
    float* o = out + (size_t)b * SS * DD + (size_t)s * DD;
    const float* y0 = (s0 >= 0) ? (g_Y + (size_t)s0 * KK) : 0;
    const float* y1 = (s1 >= 0) ? (g_Y + (size_t)s1 * KK) : 0;
    for (int d4 = threadIdx.x; d4 < DD / 4; d4 += 256) {
        float4 v = make_float4(0.f, 0.f, 0.f, 0.f);
        if (y0) {
            float4 a = *(const float4*)(y0 + d4 * 4);
            v.x += w0 * a.x; v.y += w0 * a.y; v.z += w0 * a.z; v.w += w0 * a.w;
        }
        if (y1) {
            float4 a = *(const float4*)(y1 + d4 * 4);
            v.x += w1 * a.x; v.y += w1 * a.y; v.z += w1 * a.z; v.w += w1 * a.w;
        }
        *(float4*)(o + d4 * 4) = v;
    }
}

// ---------------- launch ----------------
extern "C" void kernel_launch(void* const* d_in, const int* in_sizes, int n_in,
                              void* d_out, int out_size) {
    (void)in_sizes; (void)n_in; (void)out_size;
    const float* hs = (const float*)d_in[0];
    const float* wg = (const float*)d_in[1];
    const float* gp = (const float*)d_in[2];
    const float* up = (const float*)d_in[3];
    const float* dp = (const float*)d_in[4];
    float* out = (float*)d_out;

    static int smem_set = 0;
    if (!smem_set) {
        cudaFuncSetAttribute(gemm_kernel, cudaFuncAttributeMaxDynamicSharedMemorySize, GSMEM);
        smem_set = 1;
    }

    bf16 *Gh, *Gl, *Uh, *Ul, *Dh, *Dl, *Xh, *Xl, *Hh, *Hl;
    float *P, *Q, *Y;
    cudaGetSymbolAddress((void**)&Gh, g_Gh); cudaGetSymbolAddress((void**)&Gl, g_Gl);
    cudaGetSymbolAddress((void**)&Uh, g_Uh); cudaGetSymbolAddress((void**)&Ul, g_Ul);
    cudaGetSymbolAddress((void**)&Dh, g_Dh); cudaGetSymbolAddress((void**)&Dl, g_Dl);
    cudaGetSymbolAddress((void**)&Xh, g_Xh); cudaGetSymbolAddress((void**)&Xl, g_Xl);
    cudaGetSymbolAddress((void**)&Hh, g_Hh); cudaGetSymbolAddress((void**)&Hl, g_Hl);
    cudaGetSymbolAddress((void**)&P, g_P);   cudaGetSymbolAddress((void**)&Q, g_Q);
    cudaGetSymbolAddress((void**)&Y, g_Y);

    const int WBLK = (int)(((size_t)EE * KK * KK) / 4 / 256);   // 65536
    prep_w_kernel<<<dim3(WBLK, 3), 256>>>(gp, up, dp, Gh, Gl, Uh, Ul, Dh, Dl);

    router_kernel<<<NTOK, 128>>>(hs, wg);
    assign_kernel<<<EE, 256>>>();
    prep_x_kernel<<<dim3(SLOTP, EE), 256>>>(hs);

    dim3 ggrid(KK / 128, SLOTP / 256, EE);
    gemm_kernel<<<ggrid, 512, GSMEM>>>(Xh, Xl, Gh, Gl, P);
    gemm_kernel<<<ggrid, 512, GSMEM>>>(Xh, Xl, Uh, Ul, Q);

    const int SBLK = (int)(((size_t)EE * SLOTP * KK) / 4 / 256); // 24576
    swiglu_kernel<<<SBLK, 256>>>();

    gemm_kernel<<<ggrid, 512, GSMEM>>>(Hh, Hl, Dh, Dl, Y);
    combine_kernel<<<NTOK, 256>>>(out);
}

// round 5
// speedup vs baseline: 2.0368x; 1.1230x over previous
#include <cuda_runtime.h>
#include <cuda_bf16.h>
#include <math.h>
#include <stdint.h>

#define BB    2
#define SS    2048
#define NTOK  4096
#define DD    2048
#define EE    16
#define CAP   640
#define SLOTP 768
#define KK    2048
#define NCH2  96                  // K' = 3*2048 in chunks of 64

typedef __nv_bfloat16 bf16;

// ---------------- scratch ----------------
__device__ bf16  g_Xh[(size_t)EE * SLOTP * KK];
__device__ bf16  g_Xl[(size_t)EE * SLOTP * KK];
__device__ bf16  g_Gh[(size_t)EE * KK * KK];
__device__ bf16  g_Gl[(size_t)EE * KK * KK];
__device__ bf16  g_Uh[(size_t)EE * KK * KK];
__device__ bf16  g_Ul[(size_t)EE * KK * KK];
__device__ bf16  g_Dh[(size_t)EE * KK * KK];
__device__ bf16  g_Dl[(size_t)EE * KK * KK];
__device__ bf16  g_Hh[(size_t)EE * SLOTP * KK];
__device__ bf16  g_Hl[(size_t)EE * SLOTP * KK];
__device__ float g_Y [(size_t)EE * SLOTP * KK];
__device__ int   g_top[NTOK * 2];
__device__ float g_w[NTOK * 2];
__device__ int   g_slot[NTOK * 2];
__device__ int   g_tok[EE * CAP];
__device__ int   g_cnt[EE];

static __device__ __forceinline__ float silu_f(float p) { return p / (1.0f + __expf(-p)); }

static __device__ __forceinline__ uint32_t smem_u32(const void* p) {
    uint32_t a;
    asm("{ .reg .u64 t; cvta.to.shared.u64 t, %1; cvt.u32.u64 %0, t; }" : "=r"(a) : "l"(p));
    return a;
}
#define CP16(dst, src) asm volatile("cp.async.cg.shared.global [%0], [%1], 16;" :: "r"(dst), "l"(src))
#define CP_COMMIT()    asm volatile("cp.async.commit_group;")
#define CP_WAIT2()     asm volatile("cp.async.wait_group 2;")
#define CP_WAIT0()     asm volatile("cp.async.wait_group 0;")

static __device__ __forceinline__ void ldsm4(uint32_t* r, uint32_t a) {
    asm volatile("ldmatrix.sync.aligned.m8n8.x4.shared.b16 {%0,%1,%2,%3}, [%4];"
                 : "=r"(r[0]), "=r"(r[1]), "=r"(r[2]), "=r"(r[3]) : "r"(a));
}
static __device__ __forceinline__ void mma_bf16(float* c, const uint32_t* a, uint32_t b0, uint32_t b1) {
    asm volatile("mma.sync.aligned.m16n8k16.row.col.f32.bf16.bf16.f32 "
                 "{%0,%1,%2,%3}, {%4,%5,%6,%7}, {%8,%9}, {%0,%1,%2,%3};"
                 : "+f"(c[0]), "+f"(c[1]), "+f"(c[2]), "+f"(c[3])
                 : "r"(a[0]), "r"(a[1]), "r"(a[2]), "r"(a[3]), "r"(b0), "r"(b1));
}
static __device__ __forceinline__ void split2(float x, uint16_t& h, uint16_t& l) {
    bf16 hb = __float2bfloat16_rn(x);
    bf16 lb = __float2bfloat16_rn(x - __bfloat162float(hb));
    h = __bfloat16_as_ushort(hb);
    l = __bfloat16_as_ushort(lb);
}

// ---------------- router ----------------
__global__ void router_kernel(const float* __restrict__ hs, const float* __restrict__ wg) {
    int n = blockIdx.x, b = n & 1, s = n >> 1;
    const float* tok = hs + (size_t)b * SS * DD + (size_t)s * DD;
    float acc[EE];
#pragma unroll
    for (int e = 0; e < EE; e++) acc[e] = 0.0f;
    for (int d = threadIdx.x; d < DD; d += 128) {
        float x = tok[d];
#pragma unroll
        for (int e = 0; e < EE; e++) acc[e] += x * wg[e * DD + d];
    }
#pragma unroll
    for (int e = 0; e < EE; e++)
#pragma unroll
        for (int off = 16; off > 0; off >>= 1)
            acc[e] += __shfl_xor_sync(0xffffffffu, acc[e], off);
    __shared__ float red[4][EE];
    int warp = threadIdx.x >> 5, lane = threadIdx.x & 31;
    if (lane == 0)
#pragma unroll
        for (int e = 0; e < EE; e++) red[warp][e] = acc[e];
    __syncthreads();
    if (threadIdx.x == 0) {
        float g[EE];
#pragma unroll
        for (int e = 0; e < EE; e++) g[e] = red[0][e] + red[1][e] + red[2][e] + red[3][e];
        float mx = g[0];
#pragma unroll
        for (int e = 1; e < EE; e++) mx = fmaxf(mx, g[e]);
        float sum = 0.0f;
#pragma unroll
        for (int e = 0; e < EE; e++) { g[e] = __expf(g[e] - mx); sum += g[e]; }
        float inv = 1.0f / sum;
#pragma unroll
        for (int e = 0; e < EE; e++) g[e] *= inv;
        int e1 = 0; float v1 = g[0];
#pragma unroll
        for (int e = 1; e < EE; e++) if (g[e] > v1) { v1 = g[e]; e1 = e; }
        int e2 = -1; float v2 = -1.0f;
#pragma unroll
        for (int e = 0; e < EE; e++) if (e != e1 && g[e] > v2) { v2 = g[e]; e2 = e; }
        float denom = v1 + v2;
        const float EPS = 1.1920929e-07f;
        if (denom < EPS) denom = EPS;
        g_top[2 * n] = e1; g_top[2 * n + 1] = e2;
        g_w[2 * n] = v1 / denom; g_w[2 * n + 1] = v2 / denom;
    }
}

// ---------------- assign ----------------
__global__ void assign_kernel() {
    int e = blockIdx.x;
    __shared__ int warpsum[8];
    __shared__ int s_running;
    if (threadIdx.x == 0) s_running = 0;
    __syncthreads();
    int lane = threadIdx.x & 31, warp = threadIdx.x >> 5;
    for (int k = 0; k < 2; k++)
        for (int c0 = 0; c0 < NTOK; c0 += 256) {
            int n = c0 + threadIdx.x;
            int f = (g_top[2 * n + k] == e) ? 1 : 0;
            unsigned bal = __ballot_sync(0xffffffffu, f);
            int lpre = __popc(bal & ((1u << lane) - 1u));
            if (lane == 0) warpsum[warp] = __popc(bal);
            __syncthreads();
            int wpre = 0, tot = 0;
#pragma unroll
            for (int w = 0; w < 8; w++) { int v = warpsum[w]; if (w < warp) wpre += v; tot += v; }
            int pos = s_running + wpre + lpre;
            if (f) {
                if (pos < CAP) { g_slot[2 * n + k] = e * SLOTP + pos; g_tok[e * CAP + pos] = n; }
                else           { g_slot[2 * n + k] = -1; }
            }
            __syncthreads();
            if (threadIdx.x == 0) s_running += tot;
            __syncthreads();
        }
    if (threadIdx.x == 0) g_cnt[e] = (s_running < CAP) ? s_running : CAP;
}

// ---------------- prep: all 3 weights split fp32 -> bf16 hi/lo ----------------
__global__ void prep_w_kernel(const float* __restrict__ gp, const float* __restrict__ up,
                              const float* __restrict__ dp,
                              bf16* __restrict__ Gh, bf16* __restrict__ Gl,
                              bf16* __restrict__ Uh, bf16* __restrict__ Ul,
                              bf16* __restrict__ Dh, bf16* __restrict__ Dl) {
    const float* src = (blockIdx.y == 0) ? gp : (blockIdx.y == 1) ? up : dp;
    bf16* dh = (blockIdx.y == 0) ? Gh : (blockIdx.y == 1) ? Uh : Dh;
    bf16* dl = (blockIdx.y == 0) ? Gl : (blockIdx.y == 1) ? Ul : Dl;
    size_t i4 = (size_t)blockIdx.x * 256 + threadIdx.x;
    float4 v = *(const float4*)(src + i4 * 4);
    uint16_t h[4], l[4];
    split2(v.x, h[0], l[0]); split2(v.y, h[1], l[1]);
    split2(v.z, h[2], l[2]); split2(v.w, h[3], l[3]);
    *(uint2*)(dh + i4 * 4) = make_uint2((uint32_t)h[0] | ((uint32_t)h[1] << 16),
                                        (uint32_t)h[2] | ((uint32_t)h[3] << 16));
    *(uint2*)(dl + i4 * 4) = make_uint2((uint32_t)l[0] | ((uint32_t)l[1] << 16),
                                        (uint32_t)l[2] | ((uint32_t)l[3] << 16));
}

// ---------------- prep: gather tokens into padded slot slabs ----------------
__global__ void prep_x_kernel(const float* __restrict__ hs) {
    int e = blockIdx.y, p = blockIdx.x;
    int count = g_cnt[e];
    size_t row = (size_t)(e * SLOTP + p) * KK;
    if (p >= count) {
        for (int j = threadIdx.x; j < KK / 4; j += 256) {
            *(uint2*)(g_Xh + row + j * 4) = make_uint2(0, 0);
            *(uint2*)(g_Xl + row + j * 4) = make_uint2(0, 0);
        }
        return;
    }
    int t = g_tok[e * CAP + p];
    const float* src = hs + ((size_t)(t & 1) * SS + (size_t)(t >> 1)) * DD;
    for (int j = threadIdx.x; j < KK / 4; j += 256) {
        float4 v = *(const float4*)(src + j * 4);
        uint16_t h[4], l[4];
        split2(v.x, h[0], l[0]); split2(v.y, h[1], l[1]);
        split2(v.z, h[2], l[2]); split2(v.w, h[3], l[3]);
        *(uint2*)(g_Xh + row + j * 4) = make_uint2((uint32_t)h[0] | ((uint32_t)h[1] << 16),
                                                   (uint32_t)h[2] | ((uint32_t)h[3] << 16));
        *(uint2*)(g_Xl + row + j * 4) = make_uint2((uint32_t)l[0] | ((uint32_t)l[1] << 16),
                                                   (uint32_t)l[2] | ((uint32_t)l[3] << 16));
    }
}

// ---------------- shared GEMM geometry ----------------
#define ROWB  144
#define ASZ   (256 * ROWB)        // 36864
#define BSZ   (128 * ROWB)        // 18432
#define STG   (ASZ + BSZ)         // 55296
#define GSMEM (4 * STG)           // 221184

// ---------------- ffn1 fused: P=X G^T, Q=X U^T, H=silu(P)*Q (split bf16) ------
// BM=256, dual BN=64 outputs. 512 thr, 16 warps (8M x 2N), warp tile 32x32 per output.
__global__ void __launch_bounds__(512, 1)
ffn1_kernel(const bf16* __restrict__ Ah, const bf16* __restrict__ Al,
            const bf16* __restrict__ Gh, const bf16* __restrict__ Gl,
            const bf16* __restrict__ Uh, const bf16* __restrict__ Ul) {
    int e = blockIdx.z;
    int count = g_cnt[e];
    int m0 = blockIdx.y * 256;
    if (m0 >= count) return;
    int n0 = blockIdx.x * 64;

    extern __shared__ char smem[];
    uint32_t sb = smem_u32(smem);
    int tid = threadIdx.x, lane = tid & 31, w = tid >> 5;
    int wm = w >> 1, wn = w & 1;

    const bf16* A_h = Ah + ((size_t)e * SLOTP + m0) * KK;
    const bf16* A_l = Al + ((size_t)e * SLOTP + m0) * KK;
    const bf16* G_h = Gh + (size_t)e * KK * KK + (size_t)n0 * KK;
    const bf16* G_l = Gl + (size_t)e * KK * KK + (size_t)n0 * KK;
    const bf16* U_h = Uh + (size_t)e * KK * KK + (size_t)n0 * KK;
    const bf16* U_l = Ul + (size_t)e * KK * KK + (size_t)n0 * KK;

    uint32_t aBase[2];
#pragma unroll
    for (int mt = 0; mt < 2; mt++)
        aBase[mt] = (uint32_t)((wm * 32 + mt * 16 + (lane & 15)) * ROWB + ((lane >> 4) << 4));
    uint32_t bBase[2][2];                     // [output][p]
    {
        int grp = lane >> 3, wi = lane & 7;
#pragma unroll
        for (int o = 0; o < 2; o++)
#pragma unroll
            for (int p = 0; p < 2; p++)
                bBase[o][p] = (uint32_t)(ASZ + (o * 64 + wn * 32 + p * 16 + ((grp >> 1) << 3) + wi) * ROWB
                                         + ((grp & 1) << 4));
    }

    float accP[2][4][4], accQ[2][4][4];
#pragma unroll
    for (int i = 0; i < 2; i++)
#pragma unroll
        for (int j = 0; j < 4; j++)
#pragma unroll
            for (int q = 0; q < 4; q++) { accP[i][j][q] = 0.0f; accQ[i][j][q] = 0.0f; }

    auto load_chunk = [&](int c, int st) {
        int r = c >> 5;
        int k0 = (c & 31) << 6;
        const bf16* As = (r == 1) ? A_l : A_h;
        const bf16* Gs = (r == 2) ? G_l : G_h;
        const bf16* Us = (r == 2) ? U_l : U_h;
        uint32_t stb = sb + st * STG;
#pragma unroll
        for (int i = 0; i < 4; i++) {
            int id = tid + i * 512;
            int row = id >> 3, sub = id & 7;
            CP16(stb + row * ROWB + sub * 16, As + (size_t)row * KK + k0 + sub * 8);
        }
#pragma unroll
        for (int i = 0; i < 2; i++) {          // B: G rows 0-63, U rows 64-127
            int id = tid + i * 512;
            int row = id >> 3, sub = id & 7;
            const bf16* src = (row < 64) ? (Gs + (size_t)row * KK) : (Us + (size_t)(row - 64) * KK);
            CP16(stb + ASZ + row * ROWB + sub * 16, src + k0 + sub * 8);
        }
        CP_COMMIT();
    };

#pragma unroll
    for (int s = 0; s < 3; s++) load_chunk(s, s);

    for (int c = 0; c < NCH2; c++) {
        CP_WAIT2();
        __syncthreads();
        if (c + 3 < NCH2) load_chunk(c + 3, (c + 3) & 3);
        uint32_t base = sb + (c & 3) * STG;
#pragma unroll
        for (int ks = 0; ks < 4; ks++) {
            uint32_t off = (uint32_t)(ks * 32);
            uint32_t a[2][4], bg[2][4], bu[2][4];
            ldsm4(a[0], base + aBase[0] + off);
            ldsm4(a[1], base + aBase[1] + off);
#pragma unroll
            for (int p = 0; p < 2; p++) { ldsm4(bg[p], base + bBase[0][p] + off);
                                          ldsm4(bu[p], base + bBase[1][p] + off); }
#pragma unroll
            for (int mt = 0; mt < 2; mt++)
#pragma unroll
                for (int p = 0; p < 2; p++) {
                    mma_bf16(accP[mt][2 * p],     a[mt], bg[p][0], bg[p][1]);
                    mma_bf16(accP[mt][2 * p + 1], a[mt], bg[p][2], bg[p][3]);
                    mma_bf16(accQ[mt][2 * p],     a[mt], bu[p][0], bu[p][1]);
                    mma_bf16(accQ[mt][2 * p + 1], a[mt], bu[p][2], bu[p][3]);
                }
        }
    }
    CP_WAIT0();

    // epilogue: SwiGLU + split -> Hh/Hl
    size_t rowbase = (size_t)e * SLOTP + m0;
#pragma unroll
    for (int mt = 0; mt < 2; mt++) {
        int row = wm * 32 + mt * 16 + (lane >> 2);
#pragma unroll
        for (int half = 0; half < 2; half++) {        // acc pair (c0,c1) vs (c2,c3)
            int rr = row + half * 8;
            bf16* Hhp = g_Hh + (rowbase + rr) * KK + n0;
            bf16* Hlp = g_Hl + (rowbase + rr) * KK + n0;
#pragma unroll
            for (int nt = 0; nt < 4; nt++) {
                int col = wn * 32 + nt * 8 + ((lane & 3) << 1);
                float p0 = accP[mt][nt][2 * half],     q0 = accQ[mt][nt][2 * half];
                float p1 = accP[mt][nt][2 * half + 1], q1 = accQ[mt][nt][2 * half + 1];
                float h0 = silu_f(p0) * q0, h1 = silu_f(p1) * q1;
                uint16_t hh0, ll0, hh1, ll1;
                split2(h0, hh0, ll0); split2(h1, hh1, ll1);
                *(uint32_t*)(Hhp + col) = (uint32_t)hh0 | ((uint32_t)hh1 << 16);
                *(uint32_t*)(Hlp + col) = (uint32_t)ll0 | ((uint32_t)ll1 << 16);
            }
        }
    }
}

// ---------------- ffn2: Y = H dp^T (BM=256, BN=128) ----------------
__global__ void __launch_bounds__(512, 1)
ffn2_kernel(const bf16* __restrict__ Ah, const bf16* __restrict__ Al,
            const bf16* __restrict__ Bh, const bf16* __restrict__ Bl,
            float* __restrict__ C) {
    int e = blockIdx.z;
    int count = g_cnt[e];
    int m0 = blockIdx.y * 256;
    if (m0 >= count) return;
    int n0 = blockIdx.x * 128;

    extern __shared__ char smem[];
    uint32_t sb = smem_u32(smem);
    int tid = threadIdx.x, lane = tid & 31, w = tid >> 5;
    int wm = w >> 1, wn = w & 1;

    const bf16* A_h = Ah + ((size_t)e * SLOTP + m0) * KK;
    const bf16* A_l = Al + ((size_t)e * SLOTP + m0) * KK;
    const bf16* B_h = Bh + (size_t)e * KK * KK + (size_t)n0 * KK;
    const bf16* B_l = Bl + (size_t)e * KK * KK + (size_t)n0 * KK;

    uint32_t aBase[2];
#pragma unroll
    for (int mt = 0; mt < 2; mt++)
        aBase[mt] = (uint32_t)((wm * 32 + mt * 16 + (lane & 15)) * ROWB + ((lane >> 4) << 4));
    uint32_t bBase[4];
    {
        int grp = lane >> 3, wi = lane & 7;
#pragma unroll
        for (int p = 0; p < 4; p++)
            bBase[p] = (uint32_t)(ASZ + (wn * 64 + p * 16 + ((grp >> 1) << 3) + wi) * ROWB + ((grp & 1) << 4));
    }

    float acc[2][8][4];
#pragma unroll
    for (int i = 0; i < 2; i++)
#pragma unroll
        for (int j = 0; j < 8; j++)
#pragma unroll
            for (int q = 0; q < 4; q++) acc[i][j][q] = 0.0f;

    auto load_chunk = [&](int c, int st) {
        int r = c >> 5;
        int k0 = (c & 31) << 6;
        const bf16* As = (r == 1) ? A_l : A_h;
        const bf16* Bs = (r == 2) ? B_l : B_h;
        uint32_t stb = sb + st * STG;
#pragma unroll
        for (int i = 0; i < 4; i++) {
            int id = tid + i * 512;
            int row = id >> 3, sub = id & 7;
            CP16(stb + row * ROWB + sub * 16, As + (size_t)row * KK + k0 + sub * 8);
        }
#pragma unroll
        for (int i = 0; i < 2; i++) {
            int id = tid + i * 512;
            int row = id >> 3, sub = id & 7;
            CP16(stb + ASZ + row * ROWB + sub * 16, Bs + (size_t)row * KK + k0 + sub * 8);
        }
        CP_COMMIT();
    };

#pragma unroll
    for (int s = 0; s < 3; s++) load_chunk(s, s);

    for (int c = 0; c < NCH2; c++) {
        CP_WAIT2();
        __syncthreads();
        if (c + 3 < NCH2) load_chunk(c + 3, (c + 3) & 3);
        uint32_t base = sb + (c & 3) * STG;
#pragma unroll
        for (int ks = 0; ks < 4; ks++) {
            uint32_t off = (uint32_t)(ks * 32);
            uint32_t a[2][4], b[4][4];
            ldsm4(a[0], base + aBase[0] + off);
            ldsm4(a[1], base + aBase[1] + off);
#pragma unroll
            for (int p = 0; p < 4; p++) ldsm4(b[p], base + bBase[p] + off);
#pragma unroll
            for (int mt = 0; mt < 2; mt++)
#pragma unroll
                for (int p = 0; p < 4; p++) {
                    mma_bf16(acc[mt][2 * p],     a[mt], b[p][0], b[p][1]);
                    mma_bf16(acc[mt][2 * p + 1], a[mt], b[p][2], b[p][3]);
                }
        }
    }
    CP_WAIT0();

    float* Cb = C + ((size_t)e * SLOTP + m0) * KK + n0;
#pragma unroll
    for (int mt = 0; mt < 2; mt++) {
        int row = wm * 32 + mt * 16 + (lane >> 2);
#pragma unroll
        for (int nt = 0; nt < 8; nt++) {
            int col = wn * 64 + nt * 8 + ((lane & 3) << 1);
            *(float2*)(Cb + (size_t)row * KK + col)       = make_float2(acc[mt][nt][0], acc[mt][nt][1]);
            *(float2*)(Cb + (size_t)(row + 8) * KK + col) = make_float2(acc[mt][nt][2], acc[mt][nt][3]);
        }
    }
}

// ---------------- combine ----------------
__global__ void combine_kernel(float* __restrict__ out) {
    int n = blockIdx.x;
    int s0 = g_slot[2 * n], s1 = g_slot[2 * n + 1];
    float w0 = g_w[2 * n], w1 = g_w[2 * n + 1];
    int b = n & 1, s = n >> 1;
    float* o = out + (size_t)b * SS * DD + (size_t)s * DD;
    const float* y0 = (s0 >= 0) ? (g_Y + (size_t)s0 * KK) : 0;
    const float* y1 = (s1 >= 0) ? (g_Y + (size_t)s1 * KK) : 0;
    for (int d4 = threadIdx.x; d4 < DD / 4; d4 += 256) {
        float4 v = make_float4(0.f, 0.f, 0.f, 0.f);
        if (y0) {
            float4 a = *(const float4*)(y0 + d4 * 4);
            v.x += w0 * a.x; v.y += w0 * a.y; v.z += w0 * a.z; v.w += w0 * a.w;
        }
        if (y1) {
            float4 a = *(const float4*)(y1 + d4 * 4);
            v.x += w1 * a.x; v.y += w1 * a.y; v.z += w1 * a.z; v.w += w1 * a.w;
        }
        *(float4*)(o + d4 * 4) = v;
    }
}

// ---------------- launch ----------------
extern "C" void kernel_launch(void* const* d_in, const int* in_sizes, int n_in,
                              void* d_out, int out_size) {
    (void)in_sizes; (void)n_in; (void)out_size;
    const float* hs = (const float*)d_in[0];
    const float* wg = (const float*)d_in[1];
    const float* gp = (const float*)d_in[2];
    const float* up = (const float*)d_in[3];
    const float* dp = (const float*)d_in[4];
    float* out = (float*)d_out;

    static int smem_set = 0;
    if (!smem_set) {
        cudaFuncSetAttribute(ffn1_kernel, cudaFuncAttributeMaxDynamicSharedMemorySize, GSMEM);
        cudaFuncSetAttribute(ffn2_kernel, cudaFuncAttributeMaxDynamicSharedMemorySize, GSMEM);
        smem_set = 1;
    }

    bf16 *Gh, *Gl, *Uh, *Ul, *Dh, *Dl, *Xh, *Xl, *Hh, *Hl;
    float *Y;
    cudaGetSymbolAddress((void**)&Gh, g_Gh); cudaGetSymbolAddress((void**)&Gl, g_Gl);
    cudaGetSymbolAddress((void**)&Uh, g_Uh); cudaGetSymbolAddress((void**)&Ul, g_Ul);
    cudaGetSymbolAddress((void**)&Dh, g_Dh); cudaGetSymbolAddress((void**)&Dl, g_Dl);
    cudaGetSymbolAddress((void**)&Xh, g_Xh); cudaGetSymbolAddress((void**)&Xl, g_Xl);
    cudaGetSymbolAddress((void**)&Hh, g_Hh); cudaGetSymbolAddress((void**)&Hl, g_Hl);
    cudaGetSymbolAddress((void**)&Y, g_Y);

    const int WBLK = (int)(((size_t)EE * KK * KK) / 4 / 256);   // 65536
    prep_w_kernel<<<dim3(WBLK, 3), 256>>>(gp, up, dp, Gh, Gl, Uh, Ul, Dh, Dl);

    router_kernel<<<NTOK, 128>>>(hs, wg);
    assign_kernel<<<EE, 256>>>();
    prep_x_kernel<<<dim3(SLOTP, EE), 256>>>(hs);

    ffn1_kernel<<<dim3(KK / 64, SLOTP / 256, EE), 512, GSMEM>>>(Xh, Xl, Gh, Gl, Uh, Ul);
    ffn2_kernel<<<dim3(KK / 128, SLOTP / 256, EE), 512, GSMEM>>>(Hh, Hl, Dh, Dl, Y);
    combine_kernel<<<NTOK, 256>>>(out);
}

// round 7
// speedup vs baseline: 2.4935x; 1.2242x over previous
#include <cuda_runtime.h>
#include <cuda_bf16.h>
#include <math.h>
#include <stdint.h>

#define BB    2
#define SS    2048
#define NTOK  4096
#define DD    2048
#define EE    16
#define CAP   640
#define SLOTP 768
#define KK    2048
#define NCH2  96                  // K' = 3*2048 in chunks of 64

typedef __nv_bfloat16 bf16;

// ---------------- scratch ----------------
__device__ bf16  g_Xh[(size_t)EE * SLOTP * KK];
__device__ bf16  g_Xl[(size_t)EE * SLOTP * KK];
__device__ bf16  g_Gh[(size_t)EE * KK * KK];
__device__ bf16  g_Gl[(size_t)EE * KK * KK];
__device__ bf16  g_Uh[(size_t)EE * KK * KK];
__device__ bf16  g_Ul[(size_t)EE * KK * KK];
__device__ bf16  g_Dh[(size_t)EE * KK * KK];
__device__ bf16  g_Dl[(size_t)EE * KK * KK];
__device__ bf16  g_Hh[(size_t)EE * SLOTP * KK];
__device__ bf16  g_Hl[(size_t)EE * SLOTP * KK];
__device__ float g_Y [(size_t)EE * SLOTP * KK];
__device__ int   g_top[NTOK * 2];
__device__ float g_w[NTOK * 2];
__device__ int   g_slot[NTOK * 2];
__device__ int   g_tok[EE * CAP];
__device__ int   g_cnt[EE];

static __device__ __forceinline__ float silu_f(float p) { return p / (1.0f + __expf(-p)); }

static __device__ __forceinline__ uint32_t smem_u32(const void* p) {
    uint32_t a;
    asm("{ .reg .u64 t; cvta.to.shared.u64 t, %1; cvt.u32.u64 %0, t; }" : "=r"(a) : "l"(p));
    return a;
}
#define CP16(dst, src) asm volatile("cp.async.cg.shared.global [%0], [%1], 16;" :: "r"(dst), "l"(src))
#define CP_COMMIT()    asm volatile("cp.async.commit_group;")
#define CP_WAIT1()     asm volatile("cp.async.wait_group 1;")
#define CP_WAIT0()     asm volatile("cp.async.wait_group 0;")

static __device__ __forceinline__ void ldsm4(uint32_t* r, uint32_t a) {
    asm volatile("ldmatrix.sync.aligned.m8n8.x4.shared.b16 {%0,%1,%2,%3}, [%4];"
                 : "=r"(r[0]), "=r"(r[1]), "=r"(r[2]), "=r"(r[3]) : "r"(a));
}
static __device__ __forceinline__ void mma_bf16(float* c, const uint32_t* a, uint32_t b0, uint32_t b1) {
    asm volatile("mma.sync.aligned.m16n8k16.row.col.f32.bf16.bf16.f32 "
                 "{%0,%1,%2,%3}, {%4,%5,%6,%7}, {%8,%9}, {%0,%1,%2,%3};"
                 : "+f"(c[0]), "+f"(c[1]), "+f"(c[2]), "+f"(c[3])
                 : "r"(a[0]), "r"(a[1]), "r"(a[2]), "r"(a[3]), "r"(b0), "r"(b1));
}
static __device__ __forceinline__ void split2(float x, uint16_t& h, uint16_t& l) {
    bf16 hb = __float2bfloat16_rn(x);
    bf16 lb = __float2bfloat16_rn(x - __bfloat162float(hb));
    h = __bfloat16_as_ushort(hb);
    l = __bfloat16_as_ushort(lb);
}
// packed split of a float4 -> (hi0|hi1, hi2|hi3), (lo0|lo1, lo2|lo3)
static __device__ __forceinline__ void split4_packed(float4 v, uint2& ho, uint2& lo) {
    __nv_bfloat162 h01 = __floats2bfloat162_rn(v.x, v.y);
    __nv_bfloat162 h23 = __floats2bfloat162_rn(v.z, v.w);
    float rx = v.x - __low2float(h01), ry = v.y - __high2float(h01);
    float rz = v.z - __low2float(h23), rw = v.w - __high2float(h23);
    __nv_bfloat162 l01 = __floats2bfloat162_rn(rx, ry);
    __nv_bfloat162 l23 = __floats2bfloat162_rn(rz, rw);
    ho.x = *reinterpret_cast<uint32_t*>(&h01); ho.y = *reinterpret_cast<uint32_t*>(&h23);
    lo.x = *reinterpret_cast<uint32_t*>(&l01); lo.y = *reinterpret_cast<uint32_t*>(&l23);
}

// ---------------- router ----------------
__global__ void router_kernel(const float* __restrict__ hs, const float* __restrict__ wg) {
    int n = blockIdx.x, b = n & 1, s = n >> 1;
    const float* tok = hs + (size_t)b * SS * DD + (size_t)s * DD;
    float acc[EE];
#pragma unroll
    for (int e = 0; e < EE; e++) acc[e] = 0.0f;
    for (int d = threadIdx.x; d < DD; d += 128) {
        float x = tok[d];
#pragma unroll
        for (int e = 0; e < EE; e++) acc[e] += x * wg[e * DD + d];
    }
#pragma unroll
    for (int e = 0; e < EE; e++)
#pragma unroll
        for (int off = 16; off > 0; off >>= 1)
            acc[e] += __shfl_xor_sync(0xffffffffu, acc[e], off);
    __shared__ float red[4][EE];
    int warp = threadIdx.x >> 5, lane = threadIdx.x & 31;
    if (lane == 0)
#pragma unroll
        for (int e = 0; e < EE; e++) red[warp][e] = acc[e];
    __syncthreads();
    if (threadIdx.x == 0) {
        float g[EE];
#pragma unroll
        for (int e = 0; e < EE; e++) g[e] = red[0][e] + red[1][e] + red[2][e] + red[3][e];
        float mx = g[0];
#pragma unroll
        for (int e = 1; e < EE; e++) mx = fmaxf(mx, g[e]);
        float sum = 0.0f;
#pragma unroll
        for (int e = 0; e < EE; e++) { g[e] = __expf(g[e] - mx); sum += g[e]; }
        float inv = 1.0f / sum;
#pragma unroll
        for (int e = 0; e < EE; e++) g[e] *= inv;
        int e1 = 0; float v1 = g[0];
#pragma unroll
        for (int e = 1; e < EE; e++) if (g[e] > v1) { v1 = g[e]; e1 = e; }
        int e2 = -1; float v2 = -1.0f;
#pragma unroll
        for (int e = 0; e < EE; e++) if (e != e1 && g[e] > v2) { v2 = g[e]; e2 = e; }
        float denom = v1 + v2;
        const float EPS = 1.1920929e-07f;
        if (denom < EPS) denom = EPS;
        g_top[2 * n] = e1; g_top[2 * n + 1] = e2;
        g_w[2 * n] = v1 / denom; g_w[2 * n + 1] = v2 / denom;
    }
}

// ---------------- assign ----------------
__global__ void assign_kernel() {
    int e = blockIdx.x;
    __shared__ int warpsum[8];
    __shared__ int s_running;
    if (threadIdx.x == 0) s_running = 0;
    __syncthreads();
    int lane = threadIdx.x & 31, warp = threadIdx.x >> 5;
    for (int k = 0; k < 2; k++)
        for (int c0 = 0; c0 < NTOK; c0 += 256) {
            int n = c0 + threadIdx.x;
            int f = (g_top[2 * n + k] == e) ? 1 : 0;
            unsigned bal = __ballot_sync(0xffffffffu, f);
            int lpre = __popc(bal & ((1u << lane) - 1u));
            if (lane == 0) warpsum[warp] = __popc(bal);
            __syncthreads();
            int wpre = 0, tot = 0;
#pragma unroll
            for (int w = 0; w < 8; w++) { int v = warpsum[w]; if (w < warp) wpre += v; tot += v; }
            int pos = s_running + wpre + lpre;
            if (f) {
                if (pos < CAP) { g_slot[2 * n + k] = e * SLOTP + pos; g_tok[e * CAP + pos] = n; }
                else           { g_slot[2 * n + k] = -1; }
            }
            __syncthreads();
            if (threadIdx.x == 0) s_running += tot;
            __syncthreads();
        }
    if (threadIdx.x == 0) g_cnt[e] = (s_running < CAP) ? s_running : CAP;
}

// ---------------- prep_w: 16 elems/thread, packed converts, coalesced ---------
// Each matrix: EE*KK*KK = 67,108,864 floats = 16,777,216 float4.
// Per block: 256 thr x 4 float4 = 1024 float4  ->  16384 blocks per matrix.
__global__ void prep_w_kernel(const float* __restrict__ gp, const float* __restrict__ up,
                              const float* __restrict__ dp,
                              bf16* __restrict__ Gh, bf16* __restrict__ Gl,
                              bf16* __restrict__ Uh, bf16* __restrict__ Ul,
                              bf16* __restrict__ Dh, bf16* __restrict__ Dl) {
    const float* src = (blockIdx.y == 0) ? gp : (blockIdx.y == 1) ? up : dp;
    bf16* dh = (blockIdx.y == 0) ? Gh : (blockIdx.y == 1) ? Uh : Dh;
    bf16* dl = (blockIdx.y == 0) ? Gl : (blockIdx.y == 1) ? Ul : Dl;
    size_t blockbase = (size_t)blockIdx.x * 1024;     // in float4 units
    float4 v[4];
#pragma unroll
    for (int i = 0; i < 4; i++)
        v[i] = *(const float4*)(src + (blockbase + i * 256 + threadIdx.x) * 4);
    uint2 ho[4], lo[4];
#pragma unroll
    for (int i = 0; i < 4; i++) split4_packed(v[i], ho[i], lo[i]);
#pragma unroll
    for (int i = 0; i < 4; i++) {
        size_t idx = (blockbase + i * 256 + threadIdx.x) * 4;
        *(uint2*)(dh + idx) = ho[i];
        *(uint2*)(dl + idx) = lo[i];
    }
}

// ---------------- prep_x: gather tokens into padded slot slabs ----------------
__global__ void prep_x_kernel(const float* __restrict__ hs) {
    int e = blockIdx.y, p = blockIdx.x;
    int count = g_cnt[e];
    size_t row = (size_t)(e * SLOTP + p) * KK;
    if (p >= count) {
        for (int j = threadIdx.x; j < KK / 4; j += 256) {
            *(uint2*)(g_Xh + row + j * 4) = make_uint2(0, 0);
            *(uint2*)(g_Xl + row + j * 4) = make_uint2(0, 0);
        }
        return;
    }
    int t = g_tok[e * CAP + p];
    const float* src = hs + ((size_t)(t & 1) * SS + (size_t)(t >> 1)) * DD;
    for (int j = threadIdx.x; j < KK / 4; j += 256) {
        float4 v = *(const float4*)(src + j * 4);
        uint2 ho, lo;
        split4_packed(v, ho, lo);
        *(uint2*)(g_Xh + row + j * 4) = ho;
        *(uint2*)(g_Xl + row + j * 4) = lo;
    }
}

// ---------------- GEMM geometry: BM=128, 3 stages, 2 CTAs/SM ----------------
#define ROWB  144
#define ASZ   (128 * ROWB)        // 18432
#define BSZ   (128 * ROWB)        // 18432
#define STG   (ASZ + BSZ)         // 36864
#define GSMEM (3 * STG)           // 110592

// ---------------- ffn1 fused: dual BN=64, SwiGLU epilogue ----------------
// 256 thr, 8 warps (4M x 2N), warp tile 32 x (32+32).
__global__ void __launch_bounds__(256, 2)
ffn1_kernel(const bf16* __restrict__ Ah, const bf16* __restrict__ Al,
            const bf16* __restrict__ Gh, const bf16* __restrict__ Gl,
            const bf16* __restrict__ Uh, const bf16* __restrict__ Ul) {
    int e = blockIdx.z;
    int count = g_cnt[e];
    int m0 = blockIdx.y * 128;
    if (m0 >= count) return;
    int n0 = blockIdx.x * 64;

    extern __shared__ char smem[];
    uint32_t sb = smem_u32(smem);
    int tid = threadIdx.x, lane = tid & 31, w = tid >> 5;
    int wm = w >> 1, wn = w & 1;

    const bf16* A_h = Ah + ((size_t)e * SLOTP + m0) * KK;
    const bf16* A_l = Al + ((size_t)e * SLOTP + m0) * KK;
    const bf16* G_h = Gh + (size_t)e * KK * KK + (size_t)n0 * KK;
    const bf16* G_l = Gl + (size_t)e * KK * KK + (size_t)n0 * KK;
    const bf16* U_h = Uh + (size_t)e * KK * KK + (size_t)n0 * KK;
    const bf16* U_l = Ul + (size_t)e * KK * KK + (size_t)n0 * KK;

    uint32_t aBase[2];
#pragma unroll
    for (int mt = 0; mt < 2; mt++)
        aBase[mt] = (uint32_t)((wm * 32 + mt * 16 + (lane & 15)) * ROWB + ((lane >> 4) << 4));
    uint32_t bBase[2][2];
    {
        int grp = lane >> 3, wi = lane & 7;
#pragma unroll
        for (int o = 0; o < 2; o++)
#pragma unroll
            for (int p = 0; p < 2; p++)
                bBase[o][p] = (uint32_t)(ASZ + (o * 64 + wn * 32 + p * 16 + ((grp >> 1) << 3) + wi) * ROWB
                                         + ((grp & 1) << 4));
    }

    float accP[2][4][4], accQ[2][4][4];
#pragma unroll
    for (int i = 0; i < 2; i++)
#pragma unroll
        for (int j = 0; j < 4; j++)
#pragma unroll
            for (int q = 0; q < 4; q++) { accP[i][j][q] = 0.0f; accQ[i][j][q] = 0.0f; }

    auto load_chunk = [&](int c, int st) {
        int r = c >> 5;
        int k0 = (c & 31) << 6;
        const bf16* As = (r == 1) ? A_l : A_h;
        const bf16* Gs = (r == 2) ? G_l : G_h;
        const bf16* Us = (r == 2) ? U_l : U_h;
        uint32_t stb = sb + st * STG;
#pragma unroll
        for (int i = 0; i < 4; i++) {
            int id = tid + i * 256;
            int row = id >> 3, sub = id & 7;
            CP16(stb + row * ROWB + sub * 16, As + (size_t)row * KK + k0 + sub * 8);
        }
#pragma unroll
        for (int i = 0; i < 4; i++) {          // B: G rows 0-63, U rows 64-127
            int id = tid + i * 256;
            int row = id >> 3, sub = id & 7;
            const bf16* src = (row < 64) ? (Gs + (size_t)row * KK) : (Us + (size_t)(row - 64) * KK);
            CP16(stb + ASZ + row * ROWB + sub * 16, src + k0 + sub * 8);
        }
        CP_COMMIT();
    };

    load_chunk(0, 0);
    load_chunk(1, 1);

    for (int c = 0; c < NCH2; c++) {
        CP_WAIT1();
        __syncthreads();
        if (c + 2 < NCH2) load_chunk(c + 2, (c + 2) % 3);
        uint32_t base = sb + (c % 3) * STG;
#pragma unroll
        for (int ks = 0; ks < 4; ks++) {
            uint32_t off = (uint32_t)(ks * 32);
            uint32_t a[2][4], bg[2][4], bu[2][4];
            ldsm4(a[0], base + aBase[0] + off);
            ldsm4(a[1], base + aBase[1] + off);
#pragma unroll
            for (int p = 0; p < 2; p++) { ldsm4(bg[p], base + bBase[0][p] + off);
                                          ldsm4(bu[p], base + bBase[1][p] + off); }
#pragma unroll
            for (int mt = 0; mt < 2; mt++)
#pragma unroll
                for (int p = 0; p < 2; p++) {
                    mma_bf16(accP[mt][2 * p],     a[mt], bg[p][0], bg[p][1]);
                    mma_bf16(accP[mt][2 * p + 1], a[mt], bg[p][2], bg[p][3]);
                    mma_bf16(accQ[mt][2 * p],     a[mt], bu[p][0], bu[p][1]);
                    mma_bf16(accQ[mt][2 * p + 1], a[mt], bu[p][2], bu[p][3]);
                }
        }
    }
    CP_WAIT0();

    // epilogue: SwiGLU + split -> Hh/Hl
    size_t rowbase = (size_t)e * SLOTP + m0;
#pragma unroll
    for (int mt = 0; mt < 2; mt++) {
        int row = wm * 32 + mt * 16 + (lane >> 2);
#pragma unroll
        for (int half = 0; half < 2; half++) {
            int rr = row + half * 8;
            bf16* Hhp = g_Hh + (rowbase + rr) * KK + n0;
            bf16* Hlp = g_Hl + (rowbase + rr) * KK + n0;
#pragma unroll
            for (int nt = 0; nt < 4; nt++) {
                int col = wn * 32 + nt * 8 + ((lane & 3) << 1);
                float p0 = accP[mt][nt][2 * half],     q0 = accQ[mt][nt][2 * half];
                float p1 = accP[mt][nt][2 * half + 1], q1 = accQ[mt][nt][2 * half + 1];
                float h0 = silu_f(p0) * q0, h1 = silu_f(p1) * q1;
                uint16_t hh0, ll0, hh1, ll1;
                split2(h0, hh0, ll0); split2(h1, hh1, ll1);
                *(uint32_t*)(Hhp + col) = (uint32_t)hh0 | ((uint32_t)hh1 << 16);
                *(uint32_t*)(Hlp + col) = (uint32_t)ll0 | ((uint32_t)ll1 << 16);
            }
        }
    }
}

// ---------------- ffn2: Y = H dp^T (BM=128, BN=128, 256 thr) ----------------
__global__ void __launch_bounds__(256, 2)
ffn2_kernel(const bf16* __restrict__ Ah, const bf16* __restrict__ Al,
            const bf16* __restrict__ Bh, const bf16* __restrict__ Bl,
            float* __restrict__ C) {
    int e = blockIdx.z;
    int count = g_cnt[e];
    int m0 = blockIdx.y * 128;
    if (m0 >= count) return;
    int n0 = blockIdx.x * 128;

    extern __shared__ char smem[];
    uint32_t sb = smem_u32(smem);
    int tid = threadIdx.x, lane = tid & 31, w = tid >> 5;
    int wm = w >> 1, wn = w & 1;

    const bf16* A_h = Ah + ((size_t)e * SLOTP + m0) * KK;
    const bf16* A_l = Al + ((size_t)e * SLOTP + m0) * KK;
    const bf16* B_h = Bh + (size_t)e * KK * KK + (size_t)n0 * KK;
    const bf16* B_l = Bl + (size_t)e * KK * KK + (size_t)n0 * KK;

    uint32_t aBase[2];
#pragma unroll
    for (int mt = 0; mt < 2; mt++)
        aBase[mt] = (uint32_t)((wm * 32 + mt * 16 + (lane & 15)) * ROWB + ((lane >> 4) << 4));
    uint32_t bBase[4];
    {
        int grp = lane >> 3, wi = lane & 7;
#pragma unroll
        for (int p = 0; p < 4; p++)
            bBase[p] = (uint32_t)(ASZ + (wn * 64 + p * 16 + ((grp >> 1) << 3) + wi) * ROWB + ((grp & 1) << 4));
    }

    float acc[2][8][4];
#pragma unroll
    for (int i = 0; i < 2; i++)
#pragma unroll
        for (int j = 0; j < 8; j++)
#pragma unroll
            for (int q = 0; q < 4; q++) acc[i][j][q] = 0.0f;

    auto load_chunk = [&](int c, int st) {
        int r = c >> 5;
        int k0 = (c & 31) << 6;
        const bf16* As = (r == 1) ? A_l : A_h;
        const bf16* Bs = (r == 2) ? B_l : B_h;
        uint32_t stb = sb + st * STG;
#pragma unroll
        for (int i = 0; i < 4; i++) {
            int id = tid + i * 256;
            int row = id >> 3, sub = id & 7;
            CP16(stb + row * ROWB + sub * 16, As + (size_t)row * KK + k0 + sub * 8);
        }
#pragma unroll
        for (int i = 0; i < 4; i++) {
            int id = tid + i * 256;
            int row = id >> 3, sub = id & 7;
            CP16(stb + ASZ + row * ROWB + sub * 16, Bs + (size_t)row * KK + k0 + sub * 8);
        }
        CP_COMMIT();
    };

    load_chunk(0, 0);
    load_chunk(1, 1);

    for (int c = 0; c < NCH2; c++) {
        CP_WAIT1();
        __syncthreads();
        if (c + 2 < NCH2) load_chunk(c + 2, (c + 2) % 3);
        uint32_t base = sb + (c % 3) * STG;
#pragma unroll
        for (int ks = 0; ks < 4; ks++) {
            uint32_t off = (uint32_t)(ks * 32);
            uint32_t a[2][4], b[4][4];
            ldsm4(a[0], base + aBase[0] + off);
            ldsm4(a[1], base + aBase[1] + off);
#pragma unroll
            for (int p = 0; p < 4; p++) ldsm4(b[p], base + bBase[p] + off);
#pragma unroll
            for (int mt = 0; mt < 2; mt++)
#pragma unroll
                for (int p = 0; p < 4; p++) {
                    mma_bf16(acc[mt][2 * p],     a[mt], b[p][0], b[p][1]);
                    mma_bf16(acc[mt][2 * p + 1], a[mt], b[p][2], b[p][3]);
                }
        }
    }
    CP_WAIT0();

    float* Cb = C + ((size_t)e * SLOTP + m0) * KK + n0;
#pragma unroll
    for (int mt = 0; mt < 2; mt++) {
        int row = wm * 32 + mt * 16 + (lane >> 2);
#pragma unroll
        for (int nt = 0; nt < 8; nt++) {
            int col = wn * 64 + nt * 8 + ((lane & 3) << 1);
            *(float2*)(Cb + (size_t)row * KK + col)       = make_float2(acc[mt][nt][0], acc[mt][nt][1]);
            *(float2*)(Cb + (size_t)(row + 8) * KK + col) = make_float2(acc[mt][nt][2], acc[mt][nt][3]);
        }
    }
}

// ---------------- combine ----------------
__global__ void combine_kernel(float* __restrict__ out) {
    int n = blockIdx.x;
    int s0 = g_slot[2 * n], s1 = g_slot[2 * n + 1];
    float w0 = g_w[2 * n], w1 = g_w[2 * n + 1];
    int b = n & 1, s = n >> 1;
    float* o = out + (size_t)b * SS * DD + (size_t)s * DD;
    const float* y0 = (s0 >= 0) ? (g_Y + (size_t)s0 * KK) : 0;
    const float* y1 = (s1 >= 0) ? (g_Y + (size_t)s1 * KK) : 0;
    for (int d4 = threadIdx.x; d4 < DD / 4; d4 += 256) {
        float4 v = make_float4(0.f, 0.f, 0.f, 0.f);
        if (y0) {
            float4 a = *(const float4*)(y0 + d4 * 4);
            v.x += w0 * a.x; v.y += w0 * a.y; v.z += w0 * a.z; v.w += w0 * a.w;
        }
        if (y1) {
            float4 a = *(const float4*)(y1 + d4 * 4);
            v.x += w1 * a.x; v.y += w1 * a.y; v.z += w1 * a.z; v.w += w1 * a.w;
        }
        *(float4*)(o + d4 * 4) = v;
    }
}

// ---------------- launch ----------------
extern "C" void kernel_launch(void* const* d_in, const int* in_sizes, int n_in,
                              void* d_out, int out_size) {
    (void)in_sizes; (void)n_in; (void)out_size;
    const float* hs = (const float*)d_in[0];
    const float* wg = (const float*)d_in[1];
    const float* gp = (const float*)d_in[2];
    const float* up = (const float*)d_in[3];
    const float* dp = (const float*)d_in[4];
    float* out = (float*)d_out;

    static int smem_set = 0;
    if (!smem_set) {
        cudaFuncSetAttribute(ffn1_kernel, cudaFuncAttributeMaxDynamicSharedMemorySize, GSMEM);
        cudaFuncSetAttribute(ffn2_kernel, cudaFuncAttributeMaxDynamicSharedMemorySize, GSMEM);
        smem_set = 1;
    }

    bf16 *Gh, *Gl, *Uh, *Ul, *Dh, *Dl, *Xh, *Xl, *Hh, *Hl;
    float *Y;
    cudaGetSymbolAddress((void**)&Gh, g_Gh); cudaGetSymbolAddress((void**)&Gl, g_Gl);
    cudaGetSymbolAddress((void**)&Uh, g_Uh); cudaGetSymbolAddress((void**)&Ul, g_Ul);
    cudaGetSymbolAddress((void**)&Dh, g_Dh); cudaGetSymbolAddress((void**)&Dl, g_Dl);
    cudaGetSymbolAddress((void**)&Xh, g_Xh); cudaGetSymbolAddress((void**)&Xl, g_Xl);
    cudaGetSymbolAddress((void**)&Hh, g_Hh); cudaGetSymbolAddress((void**)&Hl, g_Hl);
    cudaGetSymbolAddress((void**)&Y, g_Y);

    // 67,108,864 floats per matrix / (256 thr * 16 floats) = 16384 blocks per matrix
    prep_w_kernel<<<dim3(16384, 3), 256>>>(gp, up, dp, Gh, Gl, Uh, Ul, Dh, Dl);

    router_kernel<<<NTOK, 128>>>(hs, wg);
    assign_kernel<<<EE, 256>>>();
    prep_x_kernel<<<dim3(SLOTP, EE), 256>>>(hs);

    ffn1_kernel<<<dim3(KK / 64, SLOTP / 128, EE), 256, GSMEM>>>(Xh, Xl, Gh, Gl, Uh, Ul);
    ffn2_kernel<<<dim3(KK / 128, SLOTP / 128, EE), 256, GSMEM>>>(Hh, Hl, Dh, Dl, Y);
    combine_kernel<<<NTOK, 256>>>(out);
}

// round 8
// speedup vs baseline: 2.7082x; 1.0861x over previous
#include <cuda_runtime.h>
#include <cuda_bf16.h>
#include <math.h>
#include <stdint.h>

#define BB    2
#define SS    2048
#define NTOK  4096
#define DD    2048
#define EE    16
#define CAP   640
#define SLOTP 768
#define KK    2048
#define NCH2  96                  // K' = 3*2048 in chunks of 64 (32 groups x 3 terms)

typedef __nv_bfloat16 bf16;

// ---------------- scratch ----------------
__device__ bf16  g_Xh[(size_t)EE * SLOTP * KK];
__device__ bf16  g_Xl[(size_t)EE * SLOTP * KK];
__device__ bf16  g_Gh[(size_t)EE * KK * KK];
__device__ bf16  g_Gl[(size_t)EE * KK * KK];
__device__ bf16  g_Uh[(size_t)EE * KK * KK];
__device__ bf16  g_Ul[(size_t)EE * KK * KK];
__device__ bf16  g_Dh[(size_t)EE * KK * KK];
__device__ bf16  g_Dl[(size_t)EE * KK * KK];
__device__ bf16  g_Hh[(size_t)EE * SLOTP * KK];
__device__ bf16  g_Hl[(size_t)EE * SLOTP * KK];
__device__ float g_Y [(size_t)EE * SLOTP * KK];
__device__ int   g_top[NTOK * 2];
__device__ float g_w[NTOK * 2];
__device__ int   g_slot[NTOK * 2];
__device__ int   g_tok[EE * CAP];
__device__ int   g_cnt[EE];

static __device__ __forceinline__ float silu_f(float p) { return p / (1.0f + __expf(-p)); }

static __device__ __forceinline__ uint32_t smem_u32(const void* p) {
    uint32_t a;
    asm("{ .reg .u64 t; cvta.to.shared.u64 t, %1; cvt.u32.u64 %0, t; }" : "=r"(a) : "l"(p));
    return a;
}
#define CP16(dst, src) asm volatile("cp.async.cg.shared.global [%0], [%1], 16;" :: "r"(dst), "l"(src))
#define CP_COMMIT()    asm volatile("cp.async.commit_group;")
#define CP_WAIT0()     asm volatile("cp.async.wait_group 0;")

static __device__ __forceinline__ void ldsm4(uint32_t* r, uint32_t a) {
    asm volatile("ldmatrix.sync.aligned.m8n8.x4.shared.b16 {%0,%1,%2,%3}, [%4];"
                 : "=r"(r[0]), "=r"(r[1]), "=r"(r[2]), "=r"(r[3]) : "r"(a));
}
static __device__ __forceinline__ void mma_bf16(float* c, const uint32_t* a, uint32_t b0, uint32_t b1) {
    asm volatile("mma.sync.aligned.m16n8k16.row.col.f32.bf16.bf16.f32 "
                 "{%0,%1,%2,%3}, {%4,%5,%6,%7}, {%8,%9}, {%0,%1,%2,%3};"
                 : "+f"(c[0]), "+f"(c[1]), "+f"(c[2]), "+f"(c[3])
                 : "r"(a[0]), "r"(a[1]), "r"(a[2]), "r"(a[3]), "r"(b0), "r"(b1));
}
static __device__ __forceinline__ void split2(float x, uint16_t& h, uint16_t& l) {
    bf16 hb = __float2bfloat16_rn(x);
    bf16 lb = __float2bfloat16_rn(x - __bfloat162float(hb));
    h = __bfloat16_as_ushort(hb);
    l = __bfloat16_as_ushort(lb);
}
// packed split of a float4 -> (hi0|hi1, hi2|hi3), (lo0|lo1, lo2|lo3)
static __device__ __forceinline__ void split4_packed(float4 v, uint2& ho, uint2& lo) {
    __nv_bfloat162 h01 = __floats2bfloat162_rn(v.x, v.y);
    __nv_bfloat162 h23 = __floats2bfloat162_rn(v.z, v.w);
    float rx = v.x - __low2float(h01), ry = v.y - __high2float(h01);
    float rz = v.z - __low2float(h23), rw = v.w - __high2float(h23);
    __nv_bfloat162 l01 = __floats2bfloat162_rn(rx, ry);
    __nv_bfloat162 l23 = __floats2bfloat162_rn(rz, rw);
    ho.x = *reinterpret_cast<uint32_t*>(&h01); ho.y = *reinterpret_cast<uint32_t*>(&h23);
    lo.x = *reinterpret_cast<uint32_t*>(&l01); lo.y = *reinterpret_cast<uint32_t*>(&l23);
}

// ---------------- router ----------------
__global__ void router_kernel(const float* __restrict__ hs, const float* __restrict__ wg) {
    int n = blockIdx.x, b = n & 1, s = n >> 1;
    const float* tok = hs + (size_t)b * SS * DD + (size_t)s * DD;
    float acc[EE];
#pragma unroll
    for (int e = 0; e < EE; e++) acc[e] = 0.0f;
    for (int d = threadIdx.x; d < DD; d += 128) {
        float x = tok[d];
#pragma unroll
        for (int e = 0; e < EE; e++) acc[e] += x * wg[e * DD + d];
    }
#pragma unroll
    for (int e = 0; e < EE; e++)
#pragma unroll
        for (int off = 16; off > 0; off >>= 1)
            acc[e] += __shfl_xor_sync(0xffffffffu, acc[e], off);
    __shared__ float red[4][EE];
    int warp = threadIdx.x >> 5, lane = threadIdx.x & 31;
    if (lane == 0)
#pragma unroll
        for (int e = 0; e < EE; e++) red[warp][e] = acc[e];
    __syncthreads();
    if (threadIdx.x == 0) {
        float g[EE];
#pragma unroll
        for (int e = 0; e < EE; e++) g[e] = red[0][e] + red[1][e] + red[2][e] + red[3][e];
        float mx = g[0];
#pragma unroll
        for (int e = 1; e < EE; e++) mx = fmaxf(mx, g[e]);
        float sum = 0.0f;
#pragma unroll
        for (int e = 0; e < EE; e++) { g[e] = __expf(g[e] - mx); sum += g[e]; }
        float inv = 1.0f / sum;
#pragma unroll
        for (int e = 0; e < EE; e++) g[e] *= inv;
        int e1 = 0; float v1 = g[0];
#pragma unroll
        for (int e = 1; e < EE; e++) if (g[e] > v1) { v1 = g[e]; e1 = e; }
        int e2 = -1; float v2 = -1.0f;
#pragma unroll
        for (int e = 0; e < EE; e++) if (e != e1 && g[e] > v2) { v2 = g[e]; e2 = e; }
        float denom = v1 + v2;
        const float EPS = 1.1920929e-07f;
        if (denom < EPS) denom = EPS;
        g_top[2 * n] = e1; g_top[2 * n + 1] = e2;
        g_w[2 * n] = v1 / denom; g_w[2 * n + 1] = v2 / denom;
    }
}

// ---------------- assign ----------------
__global__ void assign_kernel() {
    int e = blockIdx.x;
    __shared__ int warpsum[8];
    __shared__ int s_running;
    if (threadIdx.x == 0) s_running = 0;
    __syncthreads();
    int lane = threadIdx.x & 31, warp = threadIdx.x >> 5;
    for (int k = 0; k < 2; k++)
        for (int c0 = 0; c0 < NTOK; c0 += 256) {
            int n = c0 + threadIdx.x;
            int f = (g_top[2 * n + k] == e) ? 1 : 0;
            unsigned bal = __ballot_sync(0xffffffffu, f);
            int lpre = __popc(bal & ((1u << lane) - 1u));
            if (lane == 0) warpsum[warp] = __popc(bal);
            __syncthreads();
            int wpre = 0, tot = 0;
#pragma unroll
            for (int w = 0; w < 8; w++) { int v = warpsum[w]; if (w < warp) wpre += v; tot += v; }
            int pos = s_running + wpre + lpre;
            if (f) {
                if (pos < CAP) { g_slot[2 * n + k] = e * SLOTP + pos; g_tok[e * CAP + pos] = n; }
                else           { g_slot[2 * n + k] = -1; }
            }
            __syncthreads();
            if (threadIdx.x == 0) s_running += tot;
            __syncthreads();
        }
    if (threadIdx.x == 0) g_cnt[e] = (s_running < CAP) ? s_running : CAP;
}

// ---------------- prep_w: 16 elems/thread, uint4 stores ----------------
// 67,108,864 floats per matrix; 4096 floats per block -> 16384 blocks per matrix.
__global__ void prep_w_kernel(const float* __restrict__ gp, const float* __restrict__ up,
                              const float* __restrict__ dp,
                              bf16* __restrict__ Gh, bf16* __restrict__ Gl,
                              bf16* __restrict__ Uh, bf16* __restrict__ Ul,
                              bf16* __restrict__ Dh, bf16* __restrict__ Dl) {
    const float* src = (blockIdx.y == 0) ? gp : (blockIdx.y == 1) ? up : dp;
    bf16* dh = (blockIdx.y == 0) ? Gh : (blockIdx.y == 1) ? Uh : Dh;
    bf16* dl = (blockIdx.y == 0) ? Gl : (blockIdx.y == 1) ? Ul : Dl;
    size_t g = (size_t)blockIdx.x * 4096 + (size_t)threadIdx.x * 8;
#pragma unroll
    for (int pass = 0; pass < 2; pass++, g += 2048) {
        float4 a = *(const float4*)(src + g);
        float4 b = *(const float4*)(src + g + 4);
        uint2 ha, la, hb, lb;
        split4_packed(a, ha, la);
        split4_packed(b, hb, lb);
        *(uint4*)(dh + g) = make_uint4(ha.x, ha.y, hb.x, hb.y);
        *(uint4*)(dl + g) = make_uint4(la.x, la.y, lb.x, lb.y);
    }
}

// ---------------- prep_x: gather tokens into padded slot slabs ----------------
__global__ void prep_x_kernel(const float* __restrict__ hs) {
    int e = blockIdx.y, p = blockIdx.x;
    int count = g_cnt[e];
    size_t row = (size_t)(e * SLOTP + p) * KK;
    if (p >= count) {
        for (int j = threadIdx.x; j < KK / 4; j += 256) {
            *(uint2*)(g_Xh + row + j * 4) = make_uint2(0, 0);
            *(uint2*)(g_Xl + row + j * 4) = make_uint2(0, 0);
        }
        return;
    }
    int t = g_tok[e * CAP + p];
    const float* src = hs + ((size_t)(t & 1) * SS + (size_t)(t >> 1)) * DD;
    for (int j = threadIdx.x; j < KK / 4; j += 256) {
        float4 v = *(const float4*)(src + j * 4);
        uint2 ho, lo;
        split4_packed(v, ho, lo);
        *(uint2*)(g_Xh + row + j * 4) = ho;
        *(uint2*)(g_Xl + row + j * 4) = lo;
    }
}

// ---------------- GEMM geometry: BM=128, separate A/B rings of 3 slots -------
// Term order per k-group: (Ah*Bh), (Al*Bh), (Ah*Bl).
// A loads: j=0 -> Ah into slot (2k)%3, j=1 -> Al into (2k+1)%3, j=2 -> reuse (2k)%3
// B loads: j=0 -> Bh into slot (2k)%3, j=1 -> reuse (2k)%3,     j=2 -> Bl into (2k+1)%3
// (saves 1/3 of both A and B smem fills vs streaming all 3 terms)
#define ROWB  144
#define TSZ   (128 * ROWB)        // 18432 per slot
#define BOFF  (3 * TSZ)           // B ring at 55296
#define GSMEM (6 * TSZ)           // 110592 -> 2 CTAs/SM

// compute-slot helpers
static __device__ __forceinline__ int slotA_of(int k, int j) { return (2 * k + (j == 1 ? 1 : 0)) % 3; }
static __device__ __forceinline__ int slotB_of(int k, int j) { return (2 * k + (j == 2 ? 1 : 0)) % 3; }
// NOTE term order (Ah Bh),(Al Bh),(Ah Bl): A lo used at j=1, B lo at j=2.

// ---------------- ffn1 fused: dual BN=64, SwiGLU epilogue ----------------
__global__ void __launch_bounds__(256, 2)
ffn1_kernel(const bf16* __restrict__ Ah, const bf16* __restrict__ Al,
            const bf16* __restrict__ Gh, const bf16* __restrict__ Gl,
            const bf16* __restrict__ Uh, const bf16* __restrict__ Ul) {
    int e = blockIdx.z;
    int count = g_cnt[e];
    int m0 = blockIdx.y * 128;
    if (m0 >= count) return;
    int n0 = blockIdx.x * 64;

    extern __shared__ char smem[];
    uint32_t sb = smem_u32(smem);
    int tid = threadIdx.x, lane = tid & 31, w = tid >> 5;
    int wm = w >> 1, wn = w & 1;

    const bf16* A_h = Ah + ((size_t)e * SLOTP + m0) * KK;
    const bf16* A_l = Al + ((size_t)e * SLOTP + m0) * KK;
    const bf16* G_h = Gh + (size_t)e * KK * KK + (size_t)n0 * KK;
    const bf16* G_l = Gl + (size_t)e * KK * KK + (size_t)n0 * KK;
    const bf16* U_h = Uh + (size_t)e * KK * KK + (size_t)n0 * KK;
    const bf16* U_l = Ul + (size_t)e * KK * KK + (size_t)n0 * KK;

    uint32_t aBase[2];
#pragma unroll
    for (int mt = 0; mt < 2; mt++)
        aBase[mt] = (uint32_t)((wm * 32 + mt * 16 + (lane & 15)) * ROWB + ((lane >> 4) << 4));
    uint32_t bBase[2][2];
    {
        int grp = lane >> 3, wi = lane & 7;
#pragma unroll
        for (int o = 0; o < 2; o++)
#pragma unroll
            for (int p = 0; p < 2; p++)
                bBase[o][p] = (uint32_t)((o * 64 + wn * 32 + p * 16 + ((grp >> 1) << 3) + wi) * ROWB
                                         + ((grp & 1) << 4));
    }

    float accP[2][4][4], accQ[2][4][4];
#pragma unroll
    for (int i = 0; i < 2; i++)
#pragma unroll
        for (int j = 0; j < 4; j++)
#pragma unroll
            for (int q = 0; q < 4; q++) { accP[i][j][q] = 0.0f; accQ[i][j][q] = 0.0f; }

    auto loadAB = [&](int c) {
        int k = c / 3, j = c - 3 * k;
        int k0 = k << 6;
        if (j != 2) {                       // A load (j=0: hi, j=1: lo)
            const bf16* As = (j == 1) ? A_l : A_h;
            uint32_t stb = sb + (uint32_t)slotA_of(k, j) * TSZ;
#pragma unroll
            for (int i = 0; i < 4; i++) {
                int id = tid + i * 256;
                int row = id >> 3, sub = id & 7;
                CP16(stb + row * ROWB + sub * 16, As + (size_t)row * KK + k0 + sub * 8);
            }
        }
        if (j != 1) {                       // B load (j=0: hi, j=2: lo)
            const bf16* Gs = (j == 2) ? G_l : G_h;
            const bf16* Us = (j == 2) ? U_l : U_h;
            uint32_t stb = sb + BOFF + (uint32_t)slotB_of(k, j) * TSZ;
#pragma unroll
            for (int i = 0; i < 4; i++) {
                int id = tid + i * 256;
                int row = id >> 3, sub = id & 7;
                const bf16* src = (row < 64) ? (Gs + (size_t)row * KK) : (Us + (size_t)(row - 64) * KK);
                CP16(stb + row * ROWB + sub * 16, src + k0 + sub * 8);
            }
        }
        CP_COMMIT();
    };

    loadAB(0);

    for (int c = 0; c < NCH2; c++) {
        CP_WAIT0();
        __syncthreads();
        if (c + 1 < NCH2) loadAB(c + 1);
        int k = c / 3, j = c - 3 * k;
        uint32_t baseA = sb + (uint32_t)slotA_of(k, j) * TSZ;
        uint32_t baseB = sb + BOFF + (uint32_t)slotB_of(k, j) * TSZ;
#pragma unroll
        for (int ks = 0; ks < 4; ks++) {
            uint32_t off = (uint32_t)(ks * 32);
            uint32_t a[2][4], bg[2][4], bu[2][4];
            ldsm4(a[0], baseA + aBase[0] + off);
            ldsm4(a[1], baseA + aBase[1] + off);
#pragma unroll
            for (int p = 0; p < 2; p++) { ldsm4(bg[p], baseB + bBase[0][p] + off);
                                          ldsm4(bu[p], baseB + bBase[1][p] + off); }
#pragma unroll
            for (int mt = 0; mt < 2; mt++)
#pragma unroll
                for (int p = 0; p < 2; p++) {
                    mma_bf16(accP[mt][2 * p],     a[mt], bg[p][0], bg[p][1]);
                    mma_bf16(accP[mt][2 * p + 1], a[mt], bg[p][2], bg[p][3]);
                    mma_bf16(accQ[mt][2 * p],     a[mt], bu[p][0], bu[p][1]);
                    mma_bf16(accQ[mt][2 * p + 1], a[mt], bu[p][2], bu[p][3]);
                }
        }
    }

    // epilogue: SwiGLU + split -> Hh/Hl
    size_t rowbase = (size_t)e * SLOTP + m0;
#pragma unroll
    for (int mt = 0; mt < 2; mt++) {
        int row = wm * 32 + mt * 16 + (lane >> 2);
#pragma unroll
        for (int half = 0; half < 2; half++) {
            int rr = row + half * 8;
            bf16* Hhp = g_Hh + (rowbase + rr) * KK + n0;
            bf16* Hlp = g_Hl + (rowbase + rr) * KK + n0;
#pragma unroll
            for (int nt = 0; nt < 4; nt++) {
                int col = wn * 32 + nt * 8 + ((lane & 3) << 1);
                float p0 = accP[mt][nt][2 * half],     q0 = accQ[mt][nt][2 * half];
                float p1 = accP[mt][nt][2 * half + 1], q1 = accQ[mt][nt][2 * half + 1];
                float h0 = silu_f(p0) * q0, h1 = silu_f(p1) * q1;
                uint16_t hh0, ll0, hh1, ll1;
                split2(h0, hh0, ll0); split2(h1, hh1, ll1);
                *(uint32_t*)(Hhp + col) = (uint32_t)hh0 | ((uint32_t)hh1 << 16);
                *(uint32_t*)(Hlp + col) = (uint32_t)ll0 | ((uint32_t)ll1 << 16);
            }
        }
    }
}

// ---------------- ffn2: Y = H dp^T (BM=128, BN=128, 256 thr) ----------------
__global__ void __launch_bounds__(256, 2)
ffn2_kernel(const bf16* __restrict__ Ah, const bf16* __restrict__ Al,
            const bf16* __restrict__ Bh, const bf16* __restrict__ Bl,
            float* __restrict__ C) {
    int e = blockIdx.z;
    int count = g_cnt[e];
    int m0 = blockIdx.y * 128;
    if (m0 >= count) return;
    int n0 = blockIdx.x * 128;

    extern __shared__ char smem[];
    uint32_t sb = smem_u32(smem);
    int tid = threadIdx.x, lane = tid & 31, w = tid >> 5;
    int wm = w >> 1, wn = w & 1;

    const bf16* A_h = Ah + ((size_t)e * SLOTP + m0) * KK;
    const bf16* A_l = Al + ((size_t)e * SLOTP + m0) * KK;
    const bf16* B_h = Bh + (size_t)e * KK * KK + (size_t)n0 * KK;
    const bf16* B_l = Bl + (size_t)e * KK * KK + (size_t)n0 * KK;

    uint32_t aBase[2];
#pragma unroll
    for (int mt = 0; mt < 2; mt++)
        aBase[mt] = (uint32_t)((wm * 32 + mt * 16 + (lane & 15)) * ROWB + ((lane >> 4) << 4));
    uint32_t bBase[4];
    {
        int grp = lane >> 3, wi = lane & 7;
#pragma unroll
        for (int p = 0; p < 4; p++)
            bBase[p] = (uint32_t)((wn * 64 + p * 16 + ((grp >> 1) << 3) + wi) * ROWB + ((grp & 1) << 4));
    }

    float acc[2][8][4];
#pragma unroll
    for (int i = 0; i < 2; i++)
#pragma unroll
        for (int j = 0; j < 8; j++)
#pragma unroll
            for (int q = 0; q < 4; q++) acc[i][j][q] = 0.0f;

    auto loadAB = [&](int c) {
        int k = c / 3, j = c - 3 * k;
        int k0 = k << 6;
        if (j != 2) {
            const bf16* As = (j == 1) ? A_l : A_h;
            uint32_t stb = sb + (uint32_t)slotA_of(k, j) * TSZ;
#pragma unroll
            for (int i = 0; i < 4; i++) {
                int id = tid + i * 256;
                int row = id >> 3, sub = id & 7;
                CP16(stb + row * ROWB + sub * 16, As + (size_t)row * KK + k0 + sub * 8);
            }
        }
        if (j != 1) {
            const bf16* Bs = (j == 2) ? B_l : B_h;
            uint32_t stb = sb + BOFF + (uint32_t)slotB_of(k, j) * TSZ;
#pragma unroll
            for (int i = 0; i < 4; i++) {
                int id = tid + i * 256;
                int row = id >> 3, sub = id & 7;
                CP16(stb + row * ROWB + sub * 16, Bs + (size_t)row * KK + k0 + sub * 8);
            }
        }
        CP_COMMIT();
    };

    loadAB(0);

    for (int c = 0; c < NCH2; c++) {
        CP_WAIT0();
        __syncthreads();
        if (c + 1 < NCH2) loadAB(c + 1);
        int k = c / 3, j = c - 3 * k;
        uint32_t baseA = sb + (uint32_t)slotA_of(k, j) * TSZ;
        uint32_t baseB = sb + BOFF + (uint32_t)slotB_of(k, j) * TSZ;
#pragma unroll
        for (int ks = 0; ks < 4; ks++) {
            uint32_t off = (uint32_t)(ks * 32);
            uint32_t a[2][4], b[4][4];
            ldsm4(a[0], baseA + aBase[0] + off);
            ldsm4(a[1], baseA + aBase[1] + off);
#pragma unroll
            for (int p = 0; p < 4; p++) ldsm4(b[p], baseB + bBase[p] + off);
#pragma unroll
            for (int mt = 0; mt < 2; mt++)
#pragma unroll
                for (int p = 0; p < 4; p++) {
                    mma_bf16(acc[mt][2 * p],     a[mt], b[p][0], b[p][1]);
                    mma_bf16(acc[mt][2 * p + 1], a[mt], b[p][2], b[p][3]);
                }
        }
    }

    float* Cb = C + ((size_t)e * SLOTP + m0) * KK + n0;
#pragma unroll
    for (int mt = 0; mt < 2; mt++) {
        int row = wm * 32 + mt * 16 + (lane >> 2);
#pragma unroll
        for (int nt = 0; nt < 8; nt++) {
            int col = wn * 64 + nt * 8 + ((lane & 3) << 1);
            *(float2*)(Cb + (size_t)row * KK + col)       = make_float2(acc[mt][nt][0], acc[mt][nt][1]);
            *(float2*)(Cb + (size_t)(row + 8) * KK + col) = make_float2(acc[mt][nt][2], acc[mt][nt][3]);
        }
    }
}

// ---------------- combine ----------------
__global__ void combine_kernel(float* __restrict__ out) {
    int n = blockIdx.x;
    int s0 = g_slot[2 * n], s1 = g_slot[2 * n + 1];
    float w0 = g_w[2 * n], w1 = g_w[2 * n + 1];
    int b = n & 1, s = n >> 1;
    float* o = out + (size_t)b * SS * DD + (size_t)s * DD;
    const float* y0 = (s0 >= 0) ? (g_Y + (size_t)s0 * KK) : 0;
    const float* y1 = (s1 >= 0) ? (g_Y + (size_t)s1 * KK) : 0;
    for (int d4 = threadIdx.x; d4 < DD / 4; d4 += 256) {
        float4 v = make_float4(0.f, 0.f, 0.f, 0.f);
        if (y0) {
            float4 a = *(const float4*)(y0 + d4 * 4);
            v.x += w0 * a.x; v.y += w0 * a.y; v.z += w0 * a.z; v.w += w0 * a.w;
        }
        if (y1) {
            float4 a = *(const float4*)(y1 + d4 * 4);
            v.x += w1 * a.x; v.y += w1 * a.y; v.z += w1 * a.z; v.w += w1 * a.w;
        }
        *(float4*)(o + d4 * 4) = v;
    }
}

// ---------------- launch ----------------
extern "C" void kernel_launch(void* const* d_in, const int* in_sizes, int n_in,
                              void* d_out, int out_size) {
    (void)in_sizes; (void)n_in; (void)out_size;
    const float* hs = (const float*)d_in[0];
    const float* wg = (const float*)d_in[1];
    const float* gp = (const float*)d_in[2];
    const float* up = (const float*)d_in[3];
    const float* dp = (const float*)d_in[4];
    float* out = (float*)d_out;

    static int smem_set = 0;
    if (!smem_set) {
        cudaFuncSetAttribute(ffn1_kernel, cudaFuncAttributeMaxDynamicSharedMemorySize, GSMEM);
        cudaFuncSetAttribute(ffn2_kernel, cudaFuncAttributeMaxDynamicSharedMemorySize, GSMEM);
        smem_set = 1;
    }

    bf16 *Gh, *Gl, *Uh, *Ul, *Dh, *Dl, *Xh, *Xl, *Hh, *Hl;
    float *Y;
    cudaGetSymbolAddress((void**)&Gh, g_Gh); cudaGetSymbolAddress((void**)&Gl, g_Gl);
    cudaGetSymbolAddress((void**)&Uh, g_Uh); cudaGetSymbolAddress((void**)&Ul, g_Ul);
    cudaGetSymbolAddress((void**)&Dh, g_Dh); cudaGetSymbolAddress((void**)&Dl, g_Dl);
    cudaGetSymbolAddress((void**)&Xh, g_Xh); cudaGetSymbolAddress((void**)&Xl, g_Xl);
    cudaGetSymbolAddress((void**)&Hh, g_Hh); cudaGetSymbolAddress((void**)&Hl, g_Hl);
    cudaGetSymbolAddress((void**)&Y, g_Y);

    // 67,108,864 floats per matrix / (256 thr * 16 floats) = 16384 blocks per matrix
    prep_w_kernel<<<dim3(16384, 3), 256>>>(gp, up, dp, Gh, Gl, Uh, Ul, Dh, Dl);

    router_kernel<<<NTOK, 128>>>(hs, wg);
    assign_kernel<<<EE, 256>>>();
    prep_x_kernel<<<dim3(SLOTP, EE), 256>>>(hs);

    ffn1_kernel<<<dim3(KK / 64, SLOTP / 128, EE), 256, GSMEM>>>(Xh, Xl, Gh, Gl, Uh, Ul);
    ffn2_kernel<<<dim3(KK / 128, SLOTP / 128, EE), 256, GSMEM>>>(Hh, Hl, Dh, Dl, Y);
    combine_kernel<<<NTOK, 256>>>(out);
}